// round 5
// baseline (speedup 1.0000x reference)
#include <cuda_runtime.h>
#include <cuda_bf16.h>
#include <cstdint>

// ---------------- scratch (static device globals; no allocation) ----------------
__device__ float2 g_XS[64*64*64*64];   // xs spectrum, fully fftshifted. [b][c][h][w], 128 MiB
__device__ float  g_Wt[64*64*64];      // combined filter*attention weight [i][h][w]
__device__ float  g_xsp[64*64*64];     // spatial conv result [b][h][w]

// ---------------- complex helpers ----------------
__device__ __forceinline__ float2 cmul(float2 a, float2 b){
    return make_float2(fmaf(a.x, b.x, -a.y*b.y), fmaf(a.x, b.y, a.y*b.x));
}
__device__ __forceinline__ float2 cadd(float2 a, float2 b){ return make_float2(a.x+b.x, a.y+b.y); }
__device__ __forceinline__ float2 csub(float2 a, float2 b){ return make_float2(a.x-b.x, a.y-b.y); }

template<int DIR> // DIR = -1 forward, +1 inverse
__device__ __forceinline__ float2 mulJ(float2 t){
    // multiply by e^{DIR*i*pi/2}
    return (DIR < 0) ? make_float2(t.y, -t.x) : make_float2(-t.y, t.x);
}

template<int DIR>
__device__ __forceinline__ void fft8(float2 v[8]){
    float2 e0=v[0], e1=v[2], e2=v[4], e3=v[6];
    float2 o0=v[1], o1=v[3], o2=v[5], o3=v[7];
    float2 t0=cadd(e0,e2), t1=csub(e0,e2), t2=cadd(e1,e3), t3=mulJ<DIR>(csub(e1,e3));
    float2 E0=cadd(t0,t2), E1=cadd(t1,t3), E2=csub(t0,t2), E3=csub(t1,t3);
    float2 u0=cadd(o0,o2), u1=csub(o0,o2), u2=cadd(o1,o3), u3=mulJ<DIR>(csub(o1,o3));
    float2 O0=cadd(u0,u2), O1=cadd(u1,u3), O2=csub(u0,u2), O3=csub(u1,u3);
    const float s = 0.70710678118654752f;
    const float2 w1v = make_float2( s, DIR < 0 ? -s : s);
    const float2 w3v = make_float2(-s, DIR < 0 ? -s : s);
    O1 = cmul(O1, w1v);
    O2 = mulJ<DIR>(O2);
    O3 = cmul(O3, w3v);
    v[0]=cadd(E0,O0); v[4]=csub(E0,O0);
    v[1]=cadd(E1,O1); v[5]=csub(E1,O1);
    v[2]=cadd(E2,O2); v[6]=csub(E2,O2);
    v[3]=cadd(E3,O3); v[7]=csub(E3,O3);
}

// Full 2D 64x64 FFT in shared memory (stride-65 float2 rows). 512 threads.
// TW[j] = e^{DIR*2*pi*i*j/64}. Enters and exits with __syncthreads().
template<int DIR>
__device__ __forceinline__ void fft2d_64(float2* S, const float2* TW, int tid){
    const int t = tid & 7;
    const int line = tid >> 3;
    float2 v[8];
    __syncthreads();
    // ---- rows (along w) ----
    #pragma unroll
    for (int a=0;a<8;a++) v[a] = S[line*65 + a*8 + t];
    fft8<DIR>(v);
    __syncthreads();
    #pragma unroll
    for (int c=0;c<8;c++) S[line*65 + c*8 + t] = cmul(v[c], TW[t*c]);
    __syncthreads();
    #pragma unroll
    for (int bb=0;bb<8;bb++) v[bb] = S[line*65 + t*8 + bb];
    fft8<DIR>(v);
    __syncthreads();
    #pragma unroll
    for (int d=0;d<8;d++) S[line*65 + t + 8*d] = v[d];
    __syncthreads();
    // ---- columns (along h) ----
    #pragma unroll
    for (int a=0;a<8;a++) v[a] = S[(a*8+t)*65 + line];
    fft8<DIR>(v);
    __syncthreads();
    #pragma unroll
    for (int c=0;c<8;c++) S[(c*8+t)*65 + line] = cmul(v[c], TW[t*c]);
    __syncthreads();
    #pragma unroll
    for (int bb=0;bb<8;bb++) v[bb] = S[(t*8+bb)*65 + line];
    fft8<DIR>(v);
    __syncthreads();
    #pragma unroll
    for (int d=0;d<8;d++) S[(t + 8*d)*65 + line] = v[d];
    __syncthreads();
}

// ---------------- kernel A: forward FFT, all shifts folded in ----------------
__global__ __launch_bounds__(512) void k_fwd_fft(const float* __restrict__ x){
    __shared__ float2 S[64*65];
    __shared__ float2 TW[64];
    const int bx = blockIdx.x;
    const int b = bx >> 6, i = bx & 63;
    const int tid = threadIdx.x;
    if (tid < 64){
        float sn, cs;
        sincospif(-(float)tid * (1.0f/32.0f), &sn, &cs);
        TW[tid] = make_float2(cs, sn);
    }
    const float* src = x + ((size_t)bx << 12);
    for (int k = tid; k < 4096; k += 512){
        const int hh = k >> 6, ww = k & 63;
        float val = src[k];
        float sgn = ((hh + ww) & 1) ? -1.0f : 1.0f;   // spatial modulation = fftshift(h,w)
        S[hh*65 + ww] = make_float2(val*sgn, 0.0f);
    }
    fft2d_64<-1>(S, TW, tid);
    const int b2 = (b + 32) & 63, i2 = (i + 32) & 63; // fftshift of batch/channel dims
    float2* dst = g_XS + ((size_t)(b2*64 + i2) << 12);
    for (int k = tid; k < 4096; k += 512)
        dst[k] = S[(k>>6)*65 + (k&63)];
}

// ---------------- kernel B: attention matvec + log-Gabor -> Wt[i][h][w] ----------------
__global__ __launch_bounds__(256) void k_attn(const float* __restrict__ f0,
        const float* __restrict__ theta, const float* __restrict__ sigma,
        const float* __restrict__ theta0, const float* __restrict__ w1,
        const float* __restrict__ b1, const float* __restrict__ w2,
        const float* __restrict__ b2){
    __shared__ float sA[64*64];   // |xs| tile [c][w]
    __shared__ float sW[64*65];   // w1 [o][c] padded; reused as h1 [o][w]
    const int i = blockIdx.x & 63, h = blockIdx.x >> 6;
    const int tid = threadIdx.x;

    for (int k = tid; k < 4096; k += 256){
        int o = k >> 6, c = k & 63;
        sW[o*65 + c] = w1[k];
    }
    const float2* base = g_XS + (size_t)i*64*4096 + (size_t)h*64;
    for (int k = tid; k < 4096; k += 256){
        int c = k >> 6, w = k & 63;
        float2 z = base[(size_t)c*4096 + w];
        sA[c*64 + w] = sqrtf(fmaf(z.x, z.x, z.y*z.y));
    }
    __syncthreads();

    // h1[o][w] = relu(b1[o] + sum_c w1[o][c]*|xs|[c][w]); thread tile 4x4
    const int tw = tid & 15, to = tid >> 4;
    const int o0 = to*4, w0 = tw*4;
    float acc[4][4];
    #pragma unroll
    for (int j=0;j<4;j++){
        float bv = b1[o0+j];
        #pragma unroll
        for (int l=0;l<4;l++) acc[j][l] = bv;
    }
    for (int c=0;c<64;c++){
        float4 av = *(const float4*)&sA[c*64 + w0];
        float wv[4];
        #pragma unroll
        for (int j=0;j<4;j++) wv[j] = sW[(o0+j)*65 + c];
        #pragma unroll
        for (int j=0;j<4;j++){
            acc[j][0] = fmaf(wv[j], av.x, acc[j][0]);
            acc[j][1] = fmaf(wv[j], av.y, acc[j][1]);
            acc[j][2] = fmaf(wv[j], av.z, acc[j][2]);
            acc[j][3] = fmaf(wv[j], av.w, acc[j][3]);
        }
    }
    __syncthreads();
    #pragma unroll
    for (int j=0;j<4;j++)
        #pragma unroll
        for (int l=0;l<4;l++)
            sW[(o0+j)*65 + (w0+l)] = fmaxf(acc[j][l], 0.0f);
    __syncthreads();

    if (tid < 64){
        const int w = tid;
        float lg[3];
        #pragma unroll
        for (int s3=0;s3<3;s3++){
            float a = b2[s3];
            for (int o=0;o<64;o++) a = fmaf(w2[s3*64+o], sW[o*65+w], a);
            lg[s3] = a;
        }
        float mx = fmaxf(lg[0], fmaxf(lg[1], lg[2]));
        float e0 = expf(lg[0]-mx), e1 = expf(lg[1]-mx), e2 = expf(lg[2]-mx);
        float inv = 1.0f/(e0+e1+e2);
        float awv[3] = {e0*inv, e1*inv, e2*inv};
        // log-Gabor filters at this (h,w) for channel i
        float yy = 2.0f*(float)h/63.0f - 1.0f;
        float xx = 2.0f*(float)w/63.0f - 1.0f;
        float r2 = fmaf(xx, xx, fmaf(yy, yy, 1e-6f));
        float lr = 0.5f*logf(r2);
        float phi = atan2f(yy, xx);
        float wt = 0.0f;
        #pragma unroll
        for (int s3=0;s3<3;s3++){
            float lf0 = logf(f0[s3*64+i]);
            float ls  = logf(sigma[s3*64+i]);
            float d1 = lr - lf0;
            float g  = expf(-(d1*d1)/(2.0f*ls*ls));
            float d2 = phi - theta[s3*64+i];
            float t0v = theta0[s3*64+i];
            float ang = expf(-(d2*d2)/(2.0f*t0v*t0v));
            wt = fmaf(g*ang, awv[s3], wt);
        }
        g_Wt[i*4096 + h*64 + w] = wt;
    }
}

// ---------------- kernel C: 3x3 spatial conv -> g_xsp[b][h][w] ----------------
__global__ __launch_bounds__(256) void k_conv(const float* __restrict__ x,
                                              const float* __restrict__ cw){
    __shared__ float pl[18*64];
    __shared__ float cwS[64*9];
    const int b = blockIdx.x >> 2;
    const int r0 = (blockIdx.x & 3) * 16;
    const int tid = threadIdx.x;
    for (int k = tid; k < 576; k += 256) cwS[k] = cw[k];
    const int r  = tid >> 4;          // 0..15 (local row)
    const int w0 = (tid & 15) * 4;    // 0..60
    float acc[4] = {0.f, 0.f, 0.f, 0.f};
    for (int ch = 0; ch < 64; ch++){
        __syncthreads();
        const float* src = x + ((size_t)(b*64 + ch) << 12);
        for (int k = tid; k < 1152; k += 256){
            int rr = k >> 6, cc = k & 63;
            int gr = r0 + rr - 1;
            pl[k] = (gr >= 0 && gr < 64) ? src[gr*64 + cc] : 0.0f;
        }
        __syncthreads();
        float c9[9];
        #pragma unroll
        for (int q=0;q<9;q++) c9[q] = cwS[ch*9 + q];
        #pragma unroll
        for (int dy=0; dy<3; dy++){
            const float* row = &pl[(r+dy)*64];
            float m1 = (w0-1 >= 0) ? row[w0-1] : 0.0f;
            float v0 = row[w0], v1 = row[w0+1], v2 = row[w0+2], v3 = row[w0+3];
            float p4 = (w0+4 < 64) ? row[w0+4] : 0.0f;
            const float* cr = &c9[dy*3];
            acc[0] = fmaf(cr[0], m1, acc[0]); acc[0] = fmaf(cr[1], v0, acc[0]); acc[0] = fmaf(cr[2], v1, acc[0]);
            acc[1] = fmaf(cr[0], v0, acc[1]); acc[1] = fmaf(cr[1], v1, acc[1]); acc[1] = fmaf(cr[2], v2, acc[1]);
            acc[2] = fmaf(cr[0], v1, acc[2]); acc[2] = fmaf(cr[1], v2, acc[2]); acc[2] = fmaf(cr[2], v3, acc[2]);
            acc[3] = fmaf(cr[0], v2, acc[3]); acc[3] = fmaf(cr[1], v3, acc[3]); acc[3] = fmaf(cr[2], p4, acc[3]);
        }
    }
    float* dst = g_xsp + b*4096 + (r0 + r)*64 + w0;
    #pragma unroll
    for (int l=0;l<4;l++) dst[l] = acc[l];
}

// ---------------- kernel D: mask + inverse FFT + mix ----------------
__global__ __launch_bounds__(512) void k_inv(const float* __restrict__ fbs,
        const float* __restrict__ mixp, float* __restrict__ out){
    __shared__ float2 S[64*65];
    __shared__ float2 TW[64];
    const int bo = blockIdx.x >> 6, io = blockIdx.x & 63;
    const int b = (bo + 32) & 63, i = (io + 32) & 63;   // ifftshift of batch/channel dims
    const float mix = mixp[0];
    const float c1 = 1.0f - mix;
    const int tid = threadIdx.x;
    float* o = out + ((size_t)blockIdx.x << 12);
    const float* sp = g_xsp + bo*4096;
    const int sidx = (int)floorf((fbs[b*2+0] + 1.0f) * 0.5f * 64.0f);
    const int eidx = (int)floorf((fbs[b*2+1] + 1.0f) * 0.5f * 64.0f);
    const bool active = (i >= sidx) && (i < eidx);
    if (!active){
        for (int k = tid; k < 4096; k += 512) o[k] = c1 * sp[k];
        return;
    }
    if (tid < 64){
        float sn, cs;
        sincospif((float)tid * (1.0f/32.0f), &sn, &cs);
        TW[tid] = make_float2(cs, sn);
    }
    const float2* src = g_XS + ((size_t)(b*64 + i) << 12);
    const float* wr = g_Wt + i*4096;
    for (int k = tid; k < 4096; k += 512){
        int hh = k >> 6;
        float2 val = make_float2(0.0f, 0.0f);
        if (hh >= sidx && hh < eidx){
            float2 z = src[k];
            float wv = wr[k];
            val = make_float2(z.x*wv, z.y*wv);
        }
        S[hh*65 + (k & 63)] = val;
    }
    fft2d_64<1>(S, TW, tid);
    const float sc = mix * (1.0f/4096.0f);
    for (int k = tid; k < 4096; k += 512){
        int yy = k >> 6, xx = k & 63;
        float par = ((yy + xx) & 1) ? -sc : sc;      // ifftshift(h,w) -> output modulation
        o[k] = fmaf(par, S[yy*65 + xx].x, c1 * sp[k]);
    }
}

// ---------------- launch ----------------
extern "C" void kernel_launch(void* const* d_in, const int* in_sizes, int n_in,
                              void* d_out, int out_size){
    (void)in_sizes; (void)n_in; (void)out_size;
    const float* x      = (const float*)d_in[0];
    const float* f0     = (const float*)d_in[1];
    const float* theta  = (const float*)d_in[2];
    const float* sigma  = (const float*)d_in[3];
    const float* theta0 = (const float*)d_in[4];
    const float* fbs    = (const float*)d_in[5];
    const float* mix    = (const float*)d_in[6];
    const float* w1     = (const float*)d_in[7];
    const float* b1     = (const float*)d_in[8];
    const float* w2     = (const float*)d_in[9];
    const float* b2     = (const float*)d_in[10];
    const float* cw     = (const float*)d_in[11];
    float* out = (float*)d_out;

    k_fwd_fft<<<4096, 512>>>(x);
    k_attn<<<4096, 256>>>(f0, theta, sigma, theta0, w1, b1, w2, b2);
    k_conv<<<256, 256>>>(x, cw);
    k_inv<<<4096, 512>>>(fbs, mix, out);
}

// round 6
// speedup vs baseline: 1.4150x; 1.4150x over previous
#include <cuda_runtime.h>
#include <cuda_bf16.h>
#include <cstdint>

// ---------------- scratch (static device globals; no allocation) ----------------
// Complex spectrum, only for channels i in [32,64) and shifted rows h in [32,64):
//   g_XS2[b][i-32][h-32][w]  (64 x 32 x 32 x 64 float2 = 33.5 MB)
__device__ float2 g_XS2[64*32*32*64];
// Magnitudes |xs|, only for batch-slot p in [32,64) (i.e. attention batch = channel
// index i in [32,64)) and rows h in [32,64):  g_AB[i-32][c][h-32][w]  (16.8 MB)
__device__ float  g_AB [32*64*32*64];
// Combined filter*attention weight, only i,h in [32,64): g_Wt[i-32][h-32][w]
__device__ float  g_Wt [32*32*64];
// spatial conv result [b][h][w]
__device__ float  g_xsp[64*64*64];

// ---------------- complex helpers ----------------
__device__ __forceinline__ float2 cmul(float2 a, float2 b){
    return make_float2(fmaf(a.x, b.x, -a.y*b.y), fmaf(a.x, b.y, a.y*b.x));
}
__device__ __forceinline__ float2 cadd(float2 a, float2 b){ return make_float2(a.x+b.x, a.y+b.y); }
__device__ __forceinline__ float2 csub(float2 a, float2 b){ return make_float2(a.x-b.x, a.y-b.y); }

template<int DIR> // DIR = -1 forward, +1 inverse
__device__ __forceinline__ float2 mulJ(float2 t){
    return (DIR < 0) ? make_float2(t.y, -t.x) : make_float2(-t.y, t.x);
}

template<int DIR>
__device__ __forceinline__ void fft8(float2 v[8]){
    float2 e0=v[0], e1=v[2], e2=v[4], e3=v[6];
    float2 o0=v[1], o1=v[3], o2=v[5], o3=v[7];
    float2 t0=cadd(e0,e2), t1=csub(e0,e2), t2=cadd(e1,e3), t3=mulJ<DIR>(csub(e1,e3));
    float2 E0=cadd(t0,t2), E1=cadd(t1,t3), E2=csub(t0,t2), E3=csub(t1,t3);
    float2 u0=cadd(o0,o2), u1=csub(o0,o2), u2=cadd(o1,o3), u3=mulJ<DIR>(csub(o1,o3));
    float2 O0=cadd(u0,u2), O1=cadd(u1,u3), O2=csub(u0,u2), O3=csub(u1,u3);
    const float s = 0.70710678118654752f;
    const float2 w1v = make_float2( s, DIR < 0 ? -s : s);
    const float2 w3v = make_float2(-s, DIR < 0 ? -s : s);
    O1 = cmul(O1, w1v);
    O2 = mulJ<DIR>(O2);
    O3 = cmul(O3, w3v);
    v[0]=cadd(E0,O0); v[4]=csub(E0,O0);
    v[1]=cadd(E1,O1); v[5]=csub(E1,O1);
    v[2]=cadd(E2,O2); v[6]=csub(E2,O2);
    v[3]=cadd(E3,O3); v[7]=csub(E3,O3);
}

// Full 2D 64x64 FFT in shared memory (stride-65 float2 rows). 512 threads.
template<int DIR>
__device__ __forceinline__ void fft2d_64(float2* S, const float2* TW, int tid){
    const int t = tid & 7;
    const int line = tid >> 3;
    float2 v[8];
    __syncthreads();
    // ---- rows (along w) ----
    #pragma unroll
    for (int a=0;a<8;a++) v[a] = S[line*65 + a*8 + t];
    fft8<DIR>(v);
    __syncthreads();
    #pragma unroll
    for (int c=0;c<8;c++) S[line*65 + c*8 + t] = cmul(v[c], TW[t*c]);
    __syncthreads();
    #pragma unroll
    for (int bb=0;bb<8;bb++) v[bb] = S[line*65 + t*8 + bb];
    fft8<DIR>(v);
    __syncthreads();
    #pragma unroll
    for (int d=0;d<8;d++) S[line*65 + t + 8*d] = v[d];
    __syncthreads();
    // ---- columns (along h) ----
    #pragma unroll
    for (int a=0;a<8;a++) v[a] = S[(a*8+t)*65 + line];
    fft8<DIR>(v);
    __syncthreads();
    #pragma unroll
    for (int c=0;c<8;c++) S[(c*8+t)*65 + line] = cmul(v[c], TW[t*c]);
    __syncthreads();
    #pragma unroll
    for (int bb=0;bb<8;bb++) v[bb] = S[(t*8+bb)*65 + line];
    fft8<DIR>(v);
    __syncthreads();
    #pragma unroll
    for (int d=0;d<8;d++) S[(t + 8*d)*65 + line] = v[d];
    __syncthreads();
}

// ---------------- kernel A: forward FFT over needed planes only ----------------
// Plane (p,q): F[p,q] = fft2(x[p,q]).
//   complex needed   <=> q in [0,32)  (channel i = q+32)
//   magnitude needed <=> p in [0,32)  (attention batch-slot = p+32, c = (q+32)&63)
//   skip planes with p>=32 && q>=32  (3072 of 4096 remain)
// Only shifted rows h in [32,64) are ever consumed downstream.
__global__ __launch_bounds__(512) void k_fwd_fft(const float* __restrict__ x){
    __shared__ float2 S[64*65];
    __shared__ float2 TW[64];
    const int bx = blockIdx.x;
    int p, q;
    if (bx < 2048){ q = bx & 31; p = bx >> 5; }          // q in [0,32), p in [0,64)
    else { int idx = bx - 2048; p = idx & 31; q = 32 + (idx >> 5); } // p<32, q in [32,64)
    const int tid = threadIdx.x;
    if (tid < 64){
        float sn, cs;
        sincospif(-(float)tid * (1.0f/32.0f), &sn, &cs);
        TW[tid] = make_float2(cs, sn);
    }
    const float4* src4 = (const float4*)(x + ((size_t)(p*64 + q) << 12));
    for (int k = tid; k < 1024; k += 512){
        float4 v = src4[k];
        const int hh = k >> 4;
        const int w0 = (k & 15) * 4;
        float s0 = ((hh + w0) & 1) ? -1.0f : 1.0f;   // (-1)^(h+w) = fftshift(h,w)
        float2* row = &S[hh*65 + w0];
        row[0] = make_float2( v.x*s0, 0.0f);
        row[1] = make_float2(-v.y*s0, 0.0f);
        row[2] = make_float2( v.z*s0, 0.0f);
        row[3] = make_float2(-v.w*s0, 0.0f);
    }
    fft2d_64<-1>(S, TW, tid);
    if (q < 32){   // complex store: b = (p+32)&63, io = q
        const int b = (p + 32) & 63;
        float2* dst = g_XS2 + ((size_t)(b*32 + q) << 11);
        for (int k = tid; k < 2048; k += 512)
            dst[k] = S[(32 + (k >> 6))*65 + (k & 63)];
    }
    if (p < 32){   // magnitude store: io = p, c = (q+32)&63
        const int c = (q + 32) & 63;
        float* dst = g_AB + ((size_t)(p*64 + c) << 11);
        for (int k = tid; k < 2048; k += 512){
            float2 z = S[(32 + (k >> 6))*65 + (k & 63)];
            dst[k] = sqrtf(fmaf(z.x, z.x, z.y*z.y));
        }
    }
}

// ---------------- kernel B: attention matvec + log-Gabor -> Wt ----------------
// Only (i,h) with i,h in [32,64): 1024 blocks.
__global__ __launch_bounds__(256) void k_attn(const float* __restrict__ f0,
        const float* __restrict__ theta, const float* __restrict__ sigma,
        const float* __restrict__ theta0, const float* __restrict__ w1,
        const float* __restrict__ b1, const float* __restrict__ w2,
        const float* __restrict__ b2){
    __shared__ float sA[64*64];   // |xs| tile [c][w]
    __shared__ float sW[64*65];   // w1 [o][c] padded; reused as h1 [o][w]
    const int io = blockIdx.x & 31, hp = blockIdx.x >> 5;  // io,hp in [0,32)
    const int i = io + 32, h = hp + 32;
    const int tid = threadIdx.x;

    for (int k = tid; k < 4096; k += 256){
        int o = k >> 6, c = k & 63;
        sW[o*65 + c] = w1[k];
    }
    const float* base = g_AB + (((size_t)io*64) << 11) + ((size_t)hp << 6);
    for (int k = tid; k < 4096; k += 256){
        int c = k >> 6, w = k & 63;
        sA[c*64 + w] = base[((size_t)c << 11) + w];
    }
    __syncthreads();

    // h1[o][w] = relu(b1[o] + sum_c w1[o][c]*|xs|[c][w]); thread tile 4x4
    const int tw = tid & 15, to = tid >> 4;
    const int o0 = to*4, w0 = tw*4;
    float acc[4][4];
    #pragma unroll
    for (int j=0;j<4;j++){
        float bv = b1[o0+j];
        #pragma unroll
        for (int l=0;l<4;l++) acc[j][l] = bv;
    }
    for (int c=0;c<64;c++){
        float4 av = *(const float4*)&sA[c*64 + w0];
        float wv[4];
        #pragma unroll
        for (int j=0;j<4;j++) wv[j] = sW[(o0+j)*65 + c];
        #pragma unroll
        for (int j=0;j<4;j++){
            acc[j][0] = fmaf(wv[j], av.x, acc[j][0]);
            acc[j][1] = fmaf(wv[j], av.y, acc[j][1]);
            acc[j][2] = fmaf(wv[j], av.z, acc[j][2]);
            acc[j][3] = fmaf(wv[j], av.w, acc[j][3]);
        }
    }
    __syncthreads();
    #pragma unroll
    for (int j=0;j<4;j++)
        #pragma unroll
        for (int l=0;l<4;l++)
            sW[(o0+j)*65 + (w0+l)] = fmaxf(acc[j][l], 0.0f);
    __syncthreads();

    if (tid < 64){
        const int w = tid;
        float lg[3];
        #pragma unroll
        for (int s3=0;s3<3;s3++){
            float a = b2[s3];
            for (int o=0;o<64;o++) a = fmaf(w2[s3*64+o], sW[o*65+w], a);
            lg[s3] = a;
        }
        float mx = fmaxf(lg[0], fmaxf(lg[1], lg[2]));
        float e0 = expf(lg[0]-mx), e1 = expf(lg[1]-mx), e2 = expf(lg[2]-mx);
        float inv = 1.0f/(e0+e1+e2);
        float awv[3] = {e0*inv, e1*inv, e2*inv};
        float yy = 2.0f*(float)h/63.0f - 1.0f;
        float xx = 2.0f*(float)w/63.0f - 1.0f;
        float r2 = fmaf(xx, xx, fmaf(yy, yy, 1e-6f));
        float lr = 0.5f*logf(r2);
        float phi = atan2f(yy, xx);
        float wt = 0.0f;
        #pragma unroll
        for (int s3=0;s3<3;s3++){
            float lf0 = logf(f0[s3*64+i]);
            float ls  = logf(sigma[s3*64+i]);
            float d1 = lr - lf0;
            float g  = expf(-(d1*d1)/(2.0f*ls*ls));
            float d2 = phi - theta[s3*64+i];
            float t0v = theta0[s3*64+i];
            float ang = expf(-(d2*d2)/(2.0f*t0v*t0v));
            wt = fmaf(g*ang, awv[s3], wt);
        }
        g_Wt[(io*32 + hp)*64 + w] = wt;
    }
}

// ---------------- kernel C: 3x3 spatial conv -> g_xsp[b][h][w] ----------------
__global__ __launch_bounds__(256) void k_conv(const float* __restrict__ x,
                                              const float* __restrict__ cw){
    __shared__ float pl[18*64];
    __shared__ float cwS[64*9];
    const int b = blockIdx.x >> 2;
    const int r0 = (blockIdx.x & 3) * 16;
    const int tid = threadIdx.x;
    for (int k = tid; k < 576; k += 256) cwS[k] = cw[k];
    const int r  = tid >> 4;
    const int w0 = (tid & 15) * 4;
    float acc[4] = {0.f, 0.f, 0.f, 0.f};
    for (int ch = 0; ch < 64; ch++){
        __syncthreads();
        const float* src = x + ((size_t)(b*64 + ch) << 12);
        for (int k = tid; k < 1152; k += 256){
            int rr = k >> 6, cc = k & 63;
            int gr = r0 + rr - 1;
            pl[k] = (gr >= 0 && gr < 64) ? src[gr*64 + cc] : 0.0f;
        }
        __syncthreads();
        float c9[9];
        #pragma unroll
        for (int q=0;q<9;q++) c9[q] = cwS[ch*9 + q];
        #pragma unroll
        for (int dy=0; dy<3; dy++){
            const float* row = &pl[(r+dy)*64];
            float m1 = (w0-1 >= 0) ? row[w0-1] : 0.0f;
            float v0 = row[w0], v1 = row[w0+1], v2 = row[w0+2], v3 = row[w0+3];
            float p4 = (w0+4 < 64) ? row[w0+4] : 0.0f;
            const float* cr = &c9[dy*3];
            acc[0] = fmaf(cr[0], m1, acc[0]); acc[0] = fmaf(cr[1], v0, acc[0]); acc[0] = fmaf(cr[2], v1, acc[0]);
            acc[1] = fmaf(cr[0], v0, acc[1]); acc[1] = fmaf(cr[1], v1, acc[1]); acc[1] = fmaf(cr[2], v2, acc[1]);
            acc[2] = fmaf(cr[0], v1, acc[2]); acc[2] = fmaf(cr[1], v2, acc[2]); acc[2] = fmaf(cr[2], v3, acc[2]);
            acc[3] = fmaf(cr[0], v2, acc[3]); acc[3] = fmaf(cr[1], v3, acc[3]); acc[3] = fmaf(cr[2], p4, acc[3]);
        }
    }
    float* dst = g_xsp + b*4096 + (r0 + r)*64 + w0;
    #pragma unroll
    for (int l=0;l<4;l++) dst[l] = acc[l];
}

// ---------------- kernel D: mask + inverse FFT + mix ----------------
__global__ __launch_bounds__(512) void k_inv(const float* __restrict__ fbs,
        const float* __restrict__ mixp, float* __restrict__ out){
    __shared__ float2 S[64*65];
    __shared__ float2 TW[64];
    const int bo = blockIdx.x >> 6, ioo = blockIdx.x & 63;
    const int b = (bo + 32) & 63, i = (ioo + 32) & 63;   // ifftshift of batch/channel dims
    const float mix = mixp[0];
    const float c1 = 1.0f - mix;
    const int tid = threadIdx.x;
    float* o = out + ((size_t)blockIdx.x << 12);
    const float* sp = g_xsp + bo*4096;
    const int sidx = (int)floorf((fbs[b*2+0] + 1.0f) * 0.5f * 64.0f);  // in [32,64)
    const int eidx = (int)floorf((fbs[b*2+1] + 1.0f) * 0.5f * 64.0f);
    const bool active = (i >= sidx) && (i < eidx);
    if (!active){
        const float4* sp4 = (const float4*)sp;
        float4* o4 = (float4*)o;
        for (int k = tid; k < 1024; k += 512){
            float4 v = sp4[k];
            o4[k] = make_float4(c1*v.x, c1*v.y, c1*v.z, c1*v.w);
        }
        return;
    }
    // active => i in [32,64) since sidx >= 32
    if (tid < 64){
        float sn, cs;
        sincospif((float)tid * (1.0f/32.0f), &sn, &cs);
        TW[tid] = make_float2(cs, sn);
    }
    // zero spectrum, then fill masked rows [sidx, eidx)
    for (int k = tid; k < 4096; k += 512)
        S[(k>>6)*65 + (k&63)] = make_float2(0.0f, 0.0f);
    __syncthreads();
    {
        const int nrows = eidx - sidx;                   // <= 32
        const float2* src = g_XS2 + (((size_t)(b*32 + (i-32)) << 5) + (sidx - 32)) * 64;
        const float*  wr  = g_Wt + ((i-32)*32 + (sidx - 32))*64;
        for (int k = tid; k < nrows*64; k += 512){
            int rr = k >> 6, w = k & 63;
            float2 z = src[k];
            float wv = wr[rr*64 + w];
            S[(sidx + rr)*65 + w] = make_float2(z.x*wv, z.y*wv);
        }
    }
    fft2d_64<1>(S, TW, tid);
    const float sc = mix * (1.0f/4096.0f);
    for (int k = tid; k < 4096; k += 512){
        int yy = k >> 6, xx = k & 63;
        float par = ((yy + xx) & 1) ? -sc : sc;      // ifftshift(h,w) -> output modulation
        o[k] = fmaf(par, S[yy*65 + xx].x, c1 * sp[k]);
    }
}

// ---------------- launch ----------------
extern "C" void kernel_launch(void* const* d_in, const int* in_sizes, int n_in,
                              void* d_out, int out_size){
    (void)in_sizes; (void)n_in; (void)out_size;
    const float* x      = (const float*)d_in[0];
    const float* f0     = (const float*)d_in[1];
    const float* theta  = (const float*)d_in[2];
    const float* sigma  = (const float*)d_in[3];
    const float* theta0 = (const float*)d_in[4];
    const float* fbs    = (const float*)d_in[5];
    const float* mix    = (const float*)d_in[6];
    const float* w1     = (const float*)d_in[7];
    const float* b1     = (const float*)d_in[8];
    const float* w2     = (const float*)d_in[9];
    const float* b2     = (const float*)d_in[10];
    const float* cw     = (const float*)d_in[11];
    float* out = (float*)d_out;

    k_fwd_fft<<<3072, 512>>>(x);
    k_attn<<<1024, 256>>>(f0, theta, sigma, theta0, w1, b1, w2, b2);
    k_conv<<<256, 256>>>(x, cw);
    k_inv<<<4096, 512>>>(fbs, mix, out);
}

// round 7
// speedup vs baseline: 1.8852x; 1.3324x over previous
#include <cuda_runtime.h>
#include <cuda_bf16.h>
#include <cstdint>

// ---------------- scratch (static device globals; no allocation) ----------------
// Complex spectrum, only channels i in [32,64), shifted rows h in [32,64):
//   g_XS2[b][i-32][h-32][w]  (64 x 32 x 32 x 64 float2 = 33.5 MB)
__device__ float2 g_XS2[64*32*32*64];
// Magnitudes |xs|, only batch-slot p in [0,32) (attention batch = channel i=p+32),
// rows h in [32,64):  g_AB[p][c][h-32][w]  (16.8 MB)
__device__ float  g_AB [32*64*32*64];
// Combined filter*attention weight, only i,h in [32,64): g_Wt[i-32][h-32][w]
__device__ float  g_Wt [32*32*64];
// spatial conv result [b][h][w]
__device__ float  g_xsp[64*64*64];

// ---------------- packed f32x2 helpers (Blackwell) ----------------
__device__ __forceinline__ float2 cadd(float2 a, float2 b){
    float2 r;
    asm("add.rn.f32x2 %0, %1, %2;"
        : "=l"(reinterpret_cast<uint64_t&>(r))
        : "l"(reinterpret_cast<const uint64_t&>(a)),
          "l"(reinterpret_cast<const uint64_t&>(b)));
    return r;
}
__device__ __forceinline__ float2 csub(float2 a, float2 b){
    float2 r;
    asm("sub.rn.f32x2 %0, %1, %2;"
        : "=l"(reinterpret_cast<uint64_t&>(r))
        : "l"(reinterpret_cast<const uint64_t&>(a)),
          "l"(reinterpret_cast<const uint64_t&>(b)));
    return r;
}
__device__ __forceinline__ float2 ffma2(float2 a, float2 b, float2 c){
    float2 r;
    asm("fma.rn.f32x2 %0, %1, %2, %3;"
        : "=l"(reinterpret_cast<uint64_t&>(r))
        : "l"(reinterpret_cast<const uint64_t&>(a)),
          "l"(reinterpret_cast<const uint64_t&>(b)),
          "l"(reinterpret_cast<const uint64_t&>(c)));
    return r;
}

// ---------------- complex helpers ----------------
__device__ __forceinline__ float2 cmul(float2 a, float2 b){
    return make_float2(fmaf(a.x, b.x, -a.y*b.y), fmaf(a.x, b.y, a.y*b.x));
}

template<int DIR> // DIR = -1 forward, +1 inverse
__device__ __forceinline__ float2 mulJ(float2 t){
    return (DIR < 0) ? make_float2(t.y, -t.x) : make_float2(-t.y, t.x);
}

template<int DIR>
__device__ __forceinline__ void fft8(float2 v[8]){
    float2 e0=v[0], e1=v[2], e2=v[4], e3=v[6];
    float2 o0=v[1], o1=v[3], o2=v[5], o3=v[7];
    float2 t0=cadd(e0,e2), t1=csub(e0,e2), t2=cadd(e1,e3), t3=mulJ<DIR>(csub(e1,e3));
    float2 E0=cadd(t0,t2), E1=cadd(t1,t3), E2=csub(t0,t2), E3=csub(t1,t3);
    float2 u0=cadd(o0,o2), u1=csub(o0,o2), u2=cadd(o1,o3), u3=mulJ<DIR>(csub(o1,o3));
    float2 O0=cadd(u0,u2), O1=cadd(u1,u3), O2=csub(u0,u2), O3=csub(u1,u3);
    const float s = 0.70710678118654752f;
    const float2 w1v = make_float2( s, DIR < 0 ? -s : s);
    const float2 w3v = make_float2(-s, DIR < 0 ? -s : s);
    O1 = cmul(O1, w1v);
    O2 = mulJ<DIR>(O2);
    O3 = cmul(O3, w3v);
    v[0]=cadd(E0,O0); v[4]=csub(E0,O0);
    v[1]=cadd(E1,O1); v[5]=csub(E1,O1);
    v[2]=cadd(E2,O2); v[6]=csub(E2,O2);
    v[3]=cadd(E3,O3); v[7]=csub(E3,O3);
}

// Full 2D 64x64 FFT in shared memory (stride-65 float2 rows). 512 threads.
template<int DIR>
__device__ __forceinline__ void fft2d_64(float2* S, const float2* TW, int tid){
    const int t = tid & 7;
    const int line = tid >> 3;
    float2 v[8];
    __syncthreads();
    // ---- rows (along w) ----
    #pragma unroll
    for (int a=0;a<8;a++) v[a] = S[line*65 + a*8 + t];
    fft8<DIR>(v);
    __syncthreads();
    #pragma unroll
    for (int c=0;c<8;c++) S[line*65 + c*8 + t] = cmul(v[c], TW[t*c]);
    __syncthreads();
    #pragma unroll
    for (int bb=0;bb<8;bb++) v[bb] = S[line*65 + t*8 + bb];
    fft8<DIR>(v);
    __syncthreads();
    #pragma unroll
    for (int d=0;d<8;d++) S[line*65 + t + 8*d] = v[d];
    __syncthreads();
    // ---- columns (along h) ----
    #pragma unroll
    for (int a=0;a<8;a++) v[a] = S[(a*8+t)*65 + line];
    fft8<DIR>(v);
    __syncthreads();
    #pragma unroll
    for (int c=0;c<8;c++) S[(c*8+t)*65 + line] = cmul(v[c], TW[t*c]);
    __syncthreads();
    #pragma unroll
    for (int bb=0;bb<8;bb++) v[bb] = S[(t*8+bb)*65 + line];
    fft8<DIR>(v);
    __syncthreads();
    #pragma unroll
    for (int d=0;d<8;d++) S[(t + 8*d)*65 + line] = v[d];
    __syncthreads();
}

// ---------------- kernel A: forward FFT, two real planes packed per block ----------------
// Plane set (3072 needed planes -> 1536 blocks, 2 real planes per complex FFT):
//   set1: q in [0,32), p in [0,64): pairs (2m,q),(2m+1,q)  -> complex store (+mag if p<32)
//   set2: p in [0,32), q in [32,64): pairs (p,32+2m),(p,33+2m) -> mag store only
// Hermitian split: for packed Z, with mirror m(h)=(64-h)&63 (valid in shifted coords):
//   FA = 0.5*(Z(h,w) + conj Z(mh,mw)),  FB = 0.5*(Zy+Z'y, Z'x-Zx)
__global__ __launch_bounds__(512) void k_fwd_fft(const float* __restrict__ x){
    __shared__ float2 S[64*65];
    __shared__ float2 TW[64];
    const int bx = blockIdx.x;
    const int tid = threadIdx.x;
    int pA, qA, pB, qB;
    if (bx < 1024){                 // set1
        int q = bx & 31, m = bx >> 5;      // m in [0,32)
        pA = 2*m;   pB = 2*m + 1;  qA = q; qB = q;
    } else {                        // set2
        int idx = bx - 1024;               // [0,512)
        int p = idx & 31, m = idx >> 5;    // m in [0,16)
        pA = p; pB = p; qA = 32 + 2*m; qB = 33 + 2*m;
    }
    if (tid < 64){
        float sn, cs;
        sincospif(-(float)tid * (1.0f/32.0f), &sn, &cs);
        TW[tid] = make_float2(cs, sn);
    }
    const float4* srcA = (const float4*)(x + ((size_t)(pA*64 + qA) << 12));
    const float4* srcB = (const float4*)(x + ((size_t)(pB*64 + qB) << 12));
    for (int k = tid; k < 1024; k += 512){
        float4 va = srcA[k];
        float4 vb = srcB[k];
        const int hh = k >> 4;
        const int w0 = (k & 15) * 4;
        float s0 = ((hh + w0) & 1) ? -1.0f : 1.0f;   // (-1)^(h+w) = fftshift(h,w)
        float2* row = &S[hh*65 + w0];
        row[0] = make_float2( va.x*s0,  vb.x*s0);
        row[1] = make_float2(-va.y*s0, -vb.y*s0);
        row[2] = make_float2( va.z*s0,  vb.z*s0);
        row[3] = make_float2(-va.w*s0, -vb.w*s0);
    }
    fft2d_64<-1>(S, TW, tid);

    if (bx < 1024){
        // ---- complex store for both planes: b = (p+32)&63, io = q ----
        const int bA = (pA + 32) & 63, bB = (pB + 32) & 63;
        float2* dstA = g_XS2 + ((size_t)(bA*32 + qA) << 11);
        float2* dstB = g_XS2 + ((size_t)(bB*32 + qB) << 11);
        const bool do_mag = (pA < 32);
        float* magA = g_AB + ((size_t)(pA*64 + (qA + 32)) << 11);
        float* magB = g_AB + ((size_t)(pB*64 + (qB + 32)) << 11);
        for (int k = tid; k < 2048; k += 512){
            const int hh = 32 + (k >> 6);
            const int ww = k & 63;
            const int mh = 64 - hh;            // hh in [32,63] -> mh in [1,32]
            const int mw = (64 - ww) & 63;
            float2 z  = S[hh*65 + ww];
            float2 zp = S[mh*65 + mw];
            float2 fa = make_float2(0.5f*(z.x + zp.x), 0.5f*(z.y - zp.y));
            float2 fb = make_float2(0.5f*(z.y + zp.y), 0.5f*(zp.x - z.x));
            dstA[k] = fa;
            dstB[k] = fb;
            if (do_mag){
                magA[k] = sqrtf(fmaf(fa.x, fa.x, fa.y*fa.y));
                magB[k] = sqrtf(fmaf(fb.x, fb.x, fb.y*fb.y));
            }
        }
    } else {
        // ---- magnitude-only store: io = p, c = q - 32 ----
        float* magA = g_AB + ((size_t)(pA*64 + (qA - 32)) << 11);
        float* magB = g_AB + ((size_t)(pB*64 + (qB - 32)) << 11);
        for (int k = tid; k < 2048; k += 512){
            const int hh = 32 + (k >> 6);
            const int ww = k & 63;
            const int mh = 64 - hh;
            const int mw = (64 - ww) & 63;
            float2 z  = S[hh*65 + ww];
            float2 zp = S[mh*65 + mw];
            float ax = 0.5f*(z.x + zp.x), ay = 0.5f*(z.y - zp.y);
            float bx2 = 0.5f*(z.y + zp.y), by = 0.5f*(zp.x - z.x);
            magA[k] = sqrtf(fmaf(ax, ax, ay*ay));
            magB[k] = sqrtf(fmaf(bx2, bx2, by*by));
        }
    }
}

// ---------------- kernel B: attention matvec + log-Gabor -> Wt ----------------
// Only (i,h) with i,h in [32,64): 1024 blocks.
__global__ __launch_bounds__(256) void k_attn(const float* __restrict__ f0,
        const float* __restrict__ theta, const float* __restrict__ sigma,
        const float* __restrict__ theta0, const float* __restrict__ w1,
        const float* __restrict__ b1, const float* __restrict__ w2,
        const float* __restrict__ b2){
    __shared__ float sA[64*64];   // |xs| tile [c][w]
    __shared__ float sW[64*65];   // w1 [o][c] padded; reused as h1 [o][w]
    const int io = blockIdx.x & 31, hp = blockIdx.x >> 5;  // io,hp in [0,32)
    const int i = io + 32, h = hp + 32;
    const int tid = threadIdx.x;

    for (int k = tid; k < 4096; k += 256){
        int o = k >> 6, c = k & 63;
        sW[o*65 + c] = w1[k];
    }
    const float* base = g_AB + (((size_t)io*64) << 11) + ((size_t)hp << 6);
    for (int k = tid; k < 4096; k += 256){
        int c = k >> 6, w = k & 63;
        sA[c*64 + w] = base[((size_t)c << 11) + w];
    }
    __syncthreads();

    // h1[o][w] = relu(b1[o] + sum_c w1[o][c]*|xs|[c][w]); thread tile 4x4
    const int tw = tid & 15, to = tid >> 4;
    const int o0 = to*4, w0 = tw*4;
    float acc[4][4];
    #pragma unroll
    for (int j=0;j<4;j++){
        float bv = b1[o0+j];
        #pragma unroll
        for (int l=0;l<4;l++) acc[j][l] = bv;
    }
    for (int c=0;c<64;c++){
        float4 av = *(const float4*)&sA[c*64 + w0];
        float wv[4];
        #pragma unroll
        for (int j=0;j<4;j++) wv[j] = sW[(o0+j)*65 + c];
        #pragma unroll
        for (int j=0;j<4;j++){
            acc[j][0] = fmaf(wv[j], av.x, acc[j][0]);
            acc[j][1] = fmaf(wv[j], av.y, acc[j][1]);
            acc[j][2] = fmaf(wv[j], av.z, acc[j][2]);
            acc[j][3] = fmaf(wv[j], av.w, acc[j][3]);
        }
    }
    __syncthreads();
    #pragma unroll
    for (int j=0;j<4;j++)
        #pragma unroll
        for (int l=0;l<4;l++)
            sW[(o0+j)*65 + (w0+l)] = fmaxf(acc[j][l], 0.0f);
    __syncthreads();

    if (tid < 64){
        const int w = tid;
        float lg[3];
        #pragma unroll
        for (int s3=0;s3<3;s3++){
            float a = b2[s3];
            for (int o=0;o<64;o++) a = fmaf(w2[s3*64+o], sW[o*65+w], a);
            lg[s3] = a;
        }
        float mx = fmaxf(lg[0], fmaxf(lg[1], lg[2]));
        float e0 = expf(lg[0]-mx), e1 = expf(lg[1]-mx), e2 = expf(lg[2]-mx);
        float inv = 1.0f/(e0+e1+e2);
        float awv[3] = {e0*inv, e1*inv, e2*inv};
        float yy = 2.0f*(float)h/63.0f - 1.0f;
        float xx = 2.0f*(float)w/63.0f - 1.0f;
        float r2 = fmaf(xx, xx, fmaf(yy, yy, 1e-6f));
        float lr = 0.5f*logf(r2);
        float phi = atan2f(yy, xx);
        float wt = 0.0f;
        #pragma unroll
        for (int s3=0;s3<3;s3++){
            float lf0 = logf(f0[s3*64+i]);
            float ls  = logf(sigma[s3*64+i]);
            float d1 = lr - lf0;
            float g  = expf(-(d1*d1)/(2.0f*ls*ls));
            float d2 = phi - theta[s3*64+i];
            float t0v = theta0[s3*64+i];
            float ang = expf(-(d2*d2)/(2.0f*t0v*t0v));
            wt = fmaf(g*ang, awv[s3], wt);
        }
        g_Wt[(io*32 + hp)*64 + w] = wt;
    }
}

// ---------------- kernel C: 3x3 conv, channel pairs in f32x2 lanes ----------------
__global__ __launch_bounds__(256) void k_conv(const float* __restrict__ x,
                                              const float* __restrict__ cw){
    __shared__ float2 pl2[18*64];    // [row][col] -> (ch_even, ch_odd)
    __shared__ float2 cwS[32*9];     // [chpair][tap]
    const int b = blockIdx.x >> 2;
    const int r0 = (blockIdx.x & 3) * 16;
    const int tid = threadIdx.x;
    for (int k = tid; k < 288; k += 256){
        int cp = k / 9, t = k - cp*9;
        cwS[k] = make_float2(cw[(2*cp)*9 + t], cw[(2*cp+1)*9 + t]);
    }
    const int r  = tid >> 4;          // 0..15 (local row)
    const int w0 = (tid & 15) * 4;    // 0..60
    float2 acc[4];
    #pragma unroll
    for (int l=0;l<4;l++) acc[l] = make_float2(0.f, 0.f);
    const float2 zero2 = make_float2(0.f, 0.f);
    for (int cp = 0; cp < 32; cp++){
        __syncthreads();
        const float* srcA = x + ((size_t)(b*64 + 2*cp) << 12);
        const float* srcB = srcA + 4096;
        for (int k = tid; k < 1152; k += 256){
            int rr = k >> 6, cc = k & 63;
            int gr = r0 + rr - 1;
            float a = 0.f, bb = 0.f;
            if (gr >= 0 && gr < 64){ a = srcA[gr*64 + cc]; bb = srcB[gr*64 + cc]; }
            pl2[k] = make_float2(a, bb);
        }
        __syncthreads();
        float2 c9[9];
        #pragma unroll
        for (int q=0;q<9;q++) c9[q] = cwS[cp*9 + q];
        #pragma unroll
        for (int dy=0; dy<3; dy++){
            const float2* row = &pl2[(r+dy)*64];
            float2 m1 = (w0 > 0) ? row[w0-1] : zero2;
            float2 v0 = row[w0], v1 = row[w0+1], v2 = row[w0+2], v3 = row[w0+3];
            float2 p4 = (w0+4 < 64) ? row[w0+4] : zero2;
            const float2* cr = &c9[dy*3];
            acc[0] = ffma2(cr[0], m1, acc[0]); acc[0] = ffma2(cr[1], v0, acc[0]); acc[0] = ffma2(cr[2], v1, acc[0]);
            acc[1] = ffma2(cr[0], v0, acc[1]); acc[1] = ffma2(cr[1], v1, acc[1]); acc[1] = ffma2(cr[2], v2, acc[1]);
            acc[2] = ffma2(cr[0], v1, acc[2]); acc[2] = ffma2(cr[1], v2, acc[2]); acc[2] = ffma2(cr[2], v3, acc[2]);
            acc[3] = ffma2(cr[0], v2, acc[3]); acc[3] = ffma2(cr[1], v3, acc[3]); acc[3] = ffma2(cr[2], p4, acc[3]);
        }
    }
    float* dst = g_xsp + b*4096 + (r0 + r)*64 + w0;
    #pragma unroll
    for (int l=0;l<4;l++) dst[l] = acc[l].x + acc[l].y;
}

// ---------------- kernel D: mask + inverse FFT + mix ----------------
__global__ __launch_bounds__(512) void k_inv(const float* __restrict__ fbs,
        const float* __restrict__ mixp, float* __restrict__ out){
    __shared__ float2 S[64*65];
    __shared__ float2 TW[64];
    const int bo = blockIdx.x >> 6, ioo = blockIdx.x & 63;
    const int b = (bo + 32) & 63, i = (ioo + 32) & 63;   // ifftshift of batch/channel dims
    const float mix = mixp[0];
    const float c1 = 1.0f - mix;
    const int tid = threadIdx.x;
    float* o = out + ((size_t)blockIdx.x << 12);
    const float* sp = g_xsp + bo*4096;
    const int sidx = (int)floorf((fbs[b*2+0] + 1.0f) * 0.5f * 64.0f);  // in [32,64)
    const int eidx = (int)floorf((fbs[b*2+1] + 1.0f) * 0.5f * 64.0f);
    const bool active = (i >= sidx) && (i < eidx);
    if (!active){
        const float4* sp4 = (const float4*)sp;
        float4* o4 = (float4*)o;
        for (int k = tid; k < 1024; k += 512){
            float4 v = sp4[k];
            o4[k] = make_float4(c1*v.x, c1*v.y, c1*v.z, c1*v.w);
        }
        return;
    }
    if (tid < 64){
        float sn, cs;
        sincospif((float)tid * (1.0f/32.0f), &sn, &cs);
        TW[tid] = make_float2(cs, sn);
    }
    for (int k = tid; k < 4096; k += 512)
        S[(k>>6)*65 + (k&63)] = make_float2(0.0f, 0.0f);
    __syncthreads();
    {
        const int nrows = eidx - sidx;                   // <= 32
        const float2* src = g_XS2 + (((size_t)(b*32 + (i-32)) << 5) + (sidx - 32)) * 64;
        const float*  wr  = g_Wt + ((i-32)*32 + (sidx - 32))*64;
        for (int k = tid; k < nrows*64; k += 512){
            int rr = k >> 6, w = k & 63;
            float2 z = src[k];
            float wv = wr[rr*64 + w];
            S[(sidx + rr)*65 + w] = make_float2(z.x*wv, z.y*wv);
        }
    }
    fft2d_64<1>(S, TW, tid);
    const float sc = mix * (1.0f/4096.0f);
    for (int k = tid; k < 4096; k += 512){
        int yy = k >> 6, xx = k & 63;
        float par = ((yy + xx) & 1) ? -sc : sc;      // ifftshift(h,w) -> output modulation
        o[k] = fmaf(par, S[yy*65 + xx].x, c1 * sp[k]);
    }
}

// ---------------- launch ----------------
extern "C" void kernel_launch(void* const* d_in, const int* in_sizes, int n_in,
                              void* d_out, int out_size){
    (void)in_sizes; (void)n_in; (void)out_size;
    const float* x      = (const float*)d_in[0];
    const float* f0     = (const float*)d_in[1];
    const float* theta  = (const float*)d_in[2];
    const float* sigma  = (const float*)d_in[3];
    const float* theta0 = (const float*)d_in[4];
    const float* fbs    = (const float*)d_in[5];
    const float* mix    = (const float*)d_in[6];
    const float* w1     = (const float*)d_in[7];
    const float* b1     = (const float*)d_in[8];
    const float* w2     = (const float*)d_in[9];
    const float* b2     = (const float*)d_in[10];
    const float* cw     = (const float*)d_in[11];
    float* out = (float*)d_out;

    k_fwd_fft<<<1536, 512>>>(x);
    k_attn<<<1024, 256>>>(f0, theta, sigma, theta0, w1, b1, w2, b2);
    k_conv<<<256, 256>>>(x, cw);
    k_inv<<<4096, 512>>>(fbs, mix, out);
}

// round 8
// speedup vs baseline: 1.9047x; 1.0103x over previous
#include <cuda_runtime.h>
#include <cuda_fp16.h>
#include <cstdint>

// ---------------- scratch (static device globals; no allocation) ----------------
// Complex spectrum (fp16 pairs), channels i in [32,64), shifted rows h in [32,64):
//   g_XS2[b][i-32][h-32][w]  (64 x 32 x 32 x 64 half2 = 16.8 MB)
__device__ __half2 g_XS2[64*32*32*64];
// Magnitudes |xs| (fp32; feeds softmax, keep precision): g_AB[p][c][h-32][w]
__device__ float  g_AB [32*64*32*64];
// Combined filter*attention weight, only i,h in [32,64): g_Wt[i-32][h-32][w]
__device__ float  g_Wt [32*32*64];
// spatial conv result, pre-scaled by (1-mix): g_xsp[b][h][w]
__device__ float  g_xsp[64*64*64];

// ---------------- conflict-free smem swizzle for 8B FFT accesses ----------------
// bank(addr8) = low4 of swizzled col: bits0-2 = c012^c345^(r&6)^r345, bit3 = c3^r0^r3.
// Verified 2-hits-per-bank (optimal) for stride-1 and stride-8 warps in both dims.
__device__ __forceinline__ int SWA(int r, int c){
    int k = ((r & 6) ^ ((r >> 3) & 7)) ^ (((r ^ (r >> 3)) & 1) << 3);
    return (r << 6) + (c ^ ((c >> 3) & 7) ^ k);
}

// ---------------- packed f32x2 helpers (Blackwell) ----------------
__device__ __forceinline__ float2 cadd(float2 a, float2 b){
    float2 r;
    asm("add.rn.f32x2 %0, %1, %2;"
        : "=l"(reinterpret_cast<uint64_t&>(r))
        : "l"(reinterpret_cast<const uint64_t&>(a)),
          "l"(reinterpret_cast<const uint64_t&>(b)));
    return r;
}
__device__ __forceinline__ float2 csub(float2 a, float2 b){
    float2 r;
    asm("sub.rn.f32x2 %0, %1, %2;"
        : "=l"(reinterpret_cast<uint64_t&>(r))
        : "l"(reinterpret_cast<const uint64_t&>(a)),
          "l"(reinterpret_cast<const uint64_t&>(b)));
    return r;
}
__device__ __forceinline__ float2 ffma2(float2 a, float2 b, float2 c){
    float2 r;
    asm("fma.rn.f32x2 %0, %1, %2, %3;"
        : "=l"(reinterpret_cast<uint64_t&>(r))
        : "l"(reinterpret_cast<const uint64_t&>(a)),
          "l"(reinterpret_cast<const uint64_t&>(b)),
          "l"(reinterpret_cast<const uint64_t&>(c)));
    return r;
}

// ---------------- complex helpers ----------------
__device__ __forceinline__ float2 cmul(float2 a, float2 b){
    return make_float2(fmaf(a.x, b.x, -a.y*b.y), fmaf(a.x, b.y, a.y*b.x));
}

template<int DIR> // DIR = -1 forward, +1 inverse
__device__ __forceinline__ float2 mulJ(float2 t){
    return (DIR < 0) ? make_float2(t.y, -t.x) : make_float2(-t.y, t.x);
}

template<int DIR>
__device__ __forceinline__ void fft8(float2 v[8]){
    float2 e0=v[0], e1=v[2], e2=v[4], e3=v[6];
    float2 o0=v[1], o1=v[3], o2=v[5], o3=v[7];
    float2 t0=cadd(e0,e2), t1=csub(e0,e2), t2=cadd(e1,e3), t3=mulJ<DIR>(csub(e1,e3));
    float2 E0=cadd(t0,t2), E1=cadd(t1,t3), E2=csub(t0,t2), E3=csub(t1,t3);
    float2 u0=cadd(o0,o2), u1=csub(o0,o2), u2=cadd(o1,o3), u3=mulJ<DIR>(csub(o1,o3));
    float2 O0=cadd(u0,u2), O1=cadd(u1,u3), O2=csub(u0,u2), O3=csub(u1,u3);
    const float s = 0.70710678118654752f;
    const float2 w1v = make_float2( s, DIR < 0 ? -s : s);
    const float2 w3v = make_float2(-s, DIR < 0 ? -s : s);
    O1 = cmul(O1, w1v);
    O2 = mulJ<DIR>(O2);
    O3 = cmul(O3, w3v);
    v[0]=cadd(E0,O0); v[4]=csub(E0,O0);
    v[1]=cadd(E1,O1); v[5]=csub(E1,O1);
    v[2]=cadd(E2,O2); v[6]=csub(E2,O2);
    v[3]=cadd(E3,O3); v[7]=csub(E3,O3);
}

// Full 2D 64x64 FFT in swizzled shared memory. 512 threads.
template<int DIR>
__device__ __forceinline__ void fft2d_64(float2* S, const float2* TW, int tid){
    const int t = tid & 7;
    const int line = tid >> 3;
    float2 v[8];
    __syncthreads();
    // ---- rows (along w) ----
    #pragma unroll
    for (int a=0;a<8;a++) v[a] = S[SWA(line, a*8+t)];
    fft8<DIR>(v);
    #pragma unroll
    for (int c=0;c<8;c++) S[SWA(line, c*8+t)] = cmul(v[c], TW[t*c]);
    __syncthreads();
    #pragma unroll
    for (int bb=0;bb<8;bb++) v[bb] = S[SWA(line, t*8+bb)];
    fft8<DIR>(v);
    __syncthreads();
    #pragma unroll
    for (int d=0;d<8;d++) S[SWA(line, t+8*d)] = v[d];
    __syncthreads();
    // ---- columns (along h) ----
    #pragma unroll
    for (int a=0;a<8;a++) v[a] = S[SWA(a*8+t, line)];
    fft8<DIR>(v);
    #pragma unroll
    for (int c=0;c<8;c++) S[SWA(c*8+t, line)] = cmul(v[c], TW[t*c]);
    __syncthreads();
    #pragma unroll
    for (int bb=0;bb<8;bb++) v[bb] = S[SWA(t*8+bb, line)];
    fft8<DIR>(v);
    __syncthreads();
    #pragma unroll
    for (int d=0;d<8;d++) S[SWA(t+8*d, line)] = v[d];
    __syncthreads();
}

// ---------------- kernel A: forward FFT, two real planes packed per block ----------------
__global__ __launch_bounds__(512) void k_fwd_fft(const float* __restrict__ x){
    __shared__ float2 S[64*64];
    __shared__ float2 TW[64];
    const int bx = blockIdx.x;
    const int tid = threadIdx.x;
    int pA, qA, pB, qB;
    if (bx < 1024){                 // set1: q<32, all p (pairs along p)
        int q = bx & 31, m = bx >> 5;
        pA = 2*m;   pB = 2*m + 1;  qA = q; qB = q;
    } else {                        // set2: p<32, q>=32 (pairs along q)
        int idx = bx - 1024;
        int p = idx & 31, m = idx >> 5;
        pA = p; pB = p; qA = 32 + 2*m; qB = 33 + 2*m;
    }
    if (tid < 64){
        float sn, cs;
        sincospif(-(float)tid * (1.0f/32.0f), &sn, &cs);
        TW[tid] = make_float2(cs, sn);
    }
    const float4* srcA = (const float4*)(x + ((size_t)(pA*64 + qA) << 12));
    const float4* srcB = (const float4*)(x + ((size_t)(pB*64 + qB) << 12));
    for (int k = tid; k < 1024; k += 512){
        float4 va = srcA[k];
        float4 vb = srcB[k];
        const int hh = k >> 4;
        const int w0 = (k & 15) * 4;
        float s0 = ((hh + w0) & 1) ? -1.0f : 1.0f;   // (-1)^(h+w) = fftshift(h,w)
        S[SWA(hh, w0+0)] = make_float2( va.x*s0,  vb.x*s0);
        S[SWA(hh, w0+1)] = make_float2(-va.y*s0, -vb.y*s0);
        S[SWA(hh, w0+2)] = make_float2( va.z*s0,  vb.z*s0);
        S[SWA(hh, w0+3)] = make_float2(-va.w*s0, -vb.w*s0);
    }
    fft2d_64<-1>(S, TW, tid);

    if (bx < 1024){
        const int bA = (pA + 32) & 63, bB = (pB + 32) & 63;
        __half2* dstA = g_XS2 + ((size_t)(bA*32 + qA) << 11);
        __half2* dstB = g_XS2 + ((size_t)(bB*32 + qB) << 11);
        const bool do_mag = (pA < 32);
        float* magA = g_AB + ((size_t)(pA*64 + (qA + 32)) << 11);
        float* magB = g_AB + ((size_t)(pB*64 + (qB + 32)) << 11);
        for (int k = tid; k < 2048; k += 512){
            const int hh = 32 + (k >> 6);
            const int ww = k & 63;
            const int mh = 64 - hh;
            const int mw = (64 - ww) & 63;
            float2 z  = S[SWA(hh, ww)];
            float2 zp = S[SWA(mh, mw)];
            float2 fa = make_float2(0.5f*(z.x + zp.x), 0.5f*(z.y - zp.y));
            float2 fb = make_float2(0.5f*(z.y + zp.y), 0.5f*(zp.x - z.x));
            dstA[k] = __floats2half2_rn(fa.x, fa.y);
            dstB[k] = __floats2half2_rn(fb.x, fb.y);
            if (do_mag){
                magA[k] = sqrtf(fmaf(fa.x, fa.x, fa.y*fa.y));
                magB[k] = sqrtf(fmaf(fb.x, fb.x, fb.y*fb.y));
            }
        }
    } else {
        float* magA = g_AB + ((size_t)(pA*64 + (qA - 32)) << 11);
        float* magB = g_AB + ((size_t)(pB*64 + (qB - 32)) << 11);
        for (int k = tid; k < 2048; k += 512){
            const int hh = 32 + (k >> 6);
            const int ww = k & 63;
            const int mh = 64 - hh;
            const int mw = (64 - ww) & 63;
            float2 z  = S[SWA(hh, ww)];
            float2 zp = S[SWA(mh, mw)];
            float ax = 0.5f*(z.x + zp.x), ay = 0.5f*(z.y - zp.y);
            float bx2 = 0.5f*(z.y + zp.y), by = 0.5f*(zp.x - z.x);
            magA[k] = sqrtf(fmaf(ax, ax, ay*ay));
            magB[k] = sqrtf(fmaf(bx2, bx2, by*by));
        }
    }
}

// ---------------- kernel B: attention matvec + log-Gabor -> Wt ----------------
__global__ __launch_bounds__(256) void k_attn(const float* __restrict__ f0,
        const float* __restrict__ theta, const float* __restrict__ sigma,
        const float* __restrict__ theta0, const float* __restrict__ w1,
        const float* __restrict__ b1, const float* __restrict__ w2,
        const float* __restrict__ b2){
    __shared__ float sA[64*64];   // |xs| tile [c][w]
    __shared__ float sW[64*65];   // w1 [o][c] padded; reused as h1 [o][w]
    const int io = blockIdx.x & 31, hp = blockIdx.x >> 5;
    const int i = io + 32, h = hp + 32;
    const int tid = threadIdx.x;

    for (int k = tid; k < 4096; k += 256){
        int o = k >> 6, c = k & 63;
        sW[o*65 + c] = w1[k];
    }
    const float* base = g_AB + (((size_t)io*64) << 11) + ((size_t)hp << 6);
    for (int k = tid; k < 4096; k += 256){
        int c = k >> 6, w = k & 63;
        sA[c*64 + w] = base[((size_t)c << 11) + w];
    }
    __syncthreads();

    const int tw = tid & 15, to = tid >> 4;
    const int o0 = to*4, w0 = tw*4;
    float acc[4][4];
    #pragma unroll
    for (int j=0;j<4;j++){
        float bv = b1[o0+j];
        #pragma unroll
        for (int l=0;l<4;l++) acc[j][l] = bv;
    }
    for (int c=0;c<64;c++){
        float4 av = *(const float4*)&sA[c*64 + w0];
        float wv[4];
        #pragma unroll
        for (int j=0;j<4;j++) wv[j] = sW[(o0+j)*65 + c];
        #pragma unroll
        for (int j=0;j<4;j++){
            acc[j][0] = fmaf(wv[j], av.x, acc[j][0]);
            acc[j][1] = fmaf(wv[j], av.y, acc[j][1]);
            acc[j][2] = fmaf(wv[j], av.z, acc[j][2]);
            acc[j][3] = fmaf(wv[j], av.w, acc[j][3]);
        }
    }
    __syncthreads();
    #pragma unroll
    for (int j=0;j<4;j++)
        #pragma unroll
        for (int l=0;l<4;l++)
            sW[(o0+j)*65 + (w0+l)] = fmaxf(acc[j][l], 0.0f);
    __syncthreads();

    if (tid < 64){
        const int w = tid;
        float lg[3];
        #pragma unroll
        for (int s3=0;s3<3;s3++){
            float a = b2[s3];
            for (int o=0;o<64;o++) a = fmaf(w2[s3*64+o], sW[o*65+w], a);
            lg[s3] = a;
        }
        float mx = fmaxf(lg[0], fmaxf(lg[1], lg[2]));
        float e0 = expf(lg[0]-mx), e1 = expf(lg[1]-mx), e2 = expf(lg[2]-mx);
        float inv = 1.0f/(e0+e1+e2);
        float awv[3] = {e0*inv, e1*inv, e2*inv};
        float yy = 2.0f*(float)h/63.0f - 1.0f;
        float xx = 2.0f*(float)w/63.0f - 1.0f;
        float r2 = fmaf(xx, xx, fmaf(yy, yy, 1e-6f));
        float lr = 0.5f*logf(r2);
        float phi = atan2f(yy, xx);
        float wt = 0.0f;
        #pragma unroll
        for (int s3=0;s3<3;s3++){
            float lf0 = logf(f0[s3*64+i]);
            float ls  = logf(sigma[s3*64+i]);
            float d1 = lr - lf0;
            float g  = expf(-(d1*d1)/(2.0f*ls*ls));
            float d2 = phi - theta[s3*64+i];
            float t0v = theta0[s3*64+i];
            float ang = expf(-(d2*d2)/(2.0f*t0v*t0v));
            wt = fmaf(g*ang, awv[s3], wt);
        }
        g_Wt[(io*32 + hp)*64 + w] = wt;
    }
}

// ---------------- kernel C: 3x3 conv, channel pairs in f32x2 lanes ----------------
// pl2 swizzle: col stored at rot2(w) = bank = w>>2 -> conflict-free taps.
__device__ __forceinline__ int ROT2(int w){ return ((w >> 2) | (w << 4)) & 63; }

__global__ __launch_bounds__(256) void k_conv(const float* __restrict__ x,
                                              const float* __restrict__ cw,
                                              const float* __restrict__ mixp){
    __shared__ float2 pl2[10*64];    // [row][rot2(col)] -> (ch_even, ch_odd)
    __shared__ float2 cwS[32*9];
    const int b = blockIdx.x >> 3;
    const int r0 = (blockIdx.x & 7) * 8;
    const int tid = threadIdx.x;
    for (int k = tid; k < 288; k += 256){
        int cp = k / 9, t = k - cp*9;
        cwS[k] = make_float2(cw[(2*cp)*9 + t], cw[(2*cp+1)*9 + t]);
    }
    const int r  = tid >> 5;          // 0..7 (local row; one row per warp)
    const int w0 = (tid & 31) * 2;    // 0..62
    float2 acc[2];
    acc[0] = make_float2(0.f, 0.f); acc[1] = make_float2(0.f, 0.f);
    const float2 zero2 = make_float2(0.f, 0.f);
    const int srow = tid >> 4;        // staging row 0..15 (only 0..9 used)
    const int scol = (tid & 15) * 4;  // staging col group
    for (int cp = 0; cp < 32; cp++){
        __syncthreads();
        const float* srcA = x + ((size_t)(b*64 + 2*cp) << 12);
        const float* srcB = srcA + 4096;
        if (srow < 10){
            int gr = r0 + srow - 1;
            float4 a4 = make_float4(0.f,0.f,0.f,0.f), b4 = a4;
            if (gr >= 0 && gr < 64){
                a4 = *(const float4*)&srcA[gr*64 + scol];
                b4 = *(const float4*)&srcB[gr*64 + scol];
            }
            pl2[srow*64 + ROT2(scol+0)] = make_float2(a4.x, b4.x);
            pl2[srow*64 + ROT2(scol+1)] = make_float2(a4.y, b4.y);
            pl2[srow*64 + ROT2(scol+2)] = make_float2(a4.z, b4.z);
            pl2[srow*64 + ROT2(scol+3)] = make_float2(a4.w, b4.w);
        }
        __syncthreads();
        float2 c9[9];
        #pragma unroll
        for (int q=0;q<9;q++) c9[q] = cwS[cp*9 + q];
        #pragma unroll
        for (int dy=0; dy<3; dy++){
            const float2* row = &pl2[(r+dy)*64];
            float2 m1 = (w0 > 0) ? row[ROT2(w0-1)] : zero2;
            float2 v0 = row[ROT2(w0)];
            float2 v1 = row[ROT2(w0+1)];
            float2 p2 = (w0+2 < 64) ? row[ROT2(w0+2)] : zero2;
            const float2* cr = &c9[dy*3];
            acc[0] = ffma2(cr[0], m1, acc[0]); acc[0] = ffma2(cr[1], v0, acc[0]); acc[0] = ffma2(cr[2], v1, acc[0]);
            acc[1] = ffma2(cr[0], v0, acc[1]); acc[1] = ffma2(cr[1], v1, acc[1]); acc[1] = ffma2(cr[2], p2, acc[1]);
        }
    }
    const float c1 = 1.0f - mixp[0];
    float* dst = g_xsp + b*4096 + (r0 + r)*64 + w0;
    dst[0] = c1 * (acc[0].x + acc[0].y);
    dst[1] = c1 * (acc[1].x + acc[1].y);
}

// ---------------- kernel D1: broadcast base output (pure streaming copy) ----------------
__global__ __launch_bounds__(256) void k_base(float* __restrict__ out){
    const int bx = blockIdx.x;                   // (bo*64 + ioo)
    const float4* sp4 = (const float4*)(g_xsp + ((size_t)(bx >> 6) << 12));
    float4* o4 = (float4*)(out + ((size_t)bx << 12));
    const int tid = threadIdx.x;
    #pragma unroll
    for (int j = 0; j < 4; j++)
        o4[tid + 256*j] = sp4[tid + 256*j];
}

// ---------------- kernel D2: active planes only: masked inverse FFT + mix ----------------
__global__ __launch_bounds__(512) void k_inv(const float* __restrict__ fbs,
        const float* __restrict__ mixp, float* __restrict__ out){
    const int bo = blockIdx.x >> 6, ioo = blockIdx.x & 63;
    const int b = (bo + 32) & 63, i = (ioo + 32) & 63;   // ifftshift of batch/channel dims
    const int sidx = (int)floorf((fbs[b*2+0] + 1.0f) * 0.5f * 64.0f);  // in [32,64)
    const int eidx = (int)floorf((fbs[b*2+1] + 1.0f) * 0.5f * 64.0f);
    if (i < sidx || i >= eidx) return;           // inactive: k_base already wrote it

    __shared__ float2 S[64*64];
    __shared__ float2 TW[64];
    const int tid = threadIdx.x;
    const float mix = mixp[0];
    float* o = out + ((size_t)blockIdx.x << 12);
    const float* sp = g_xsp + bo*4096;           // already scaled by (1-mix)
    if (tid < 64){
        float sn, cs;
        sincospif((float)tid * (1.0f/32.0f), &sn, &cs);
        TW[tid] = make_float2(cs, sn);
    }
    for (int k = tid; k < 4096; k += 512)
        S[k] = make_float2(0.0f, 0.0f);          // zero all (swizzle-agnostic)
    __syncthreads();
    {
        const int nrows = eidx - sidx;           // <= 32
        const __half2* src = g_XS2 + (((size_t)(b*32 + (i-32)) << 5) + (sidx - 32)) * 64;
        const float*   wr  = g_Wt + ((i-32)*32 + (sidx - 32))*64;
        for (int k = tid; k < nrows*64; k += 512){
            int rr = k >> 6, w = k & 63;
            float2 z = __half22float2(src[k]);
            float wv = wr[rr*64 + w];
            S[SWA(sidx + rr, w)] = make_float2(z.x*wv, z.y*wv);
        }
    }
    fft2d_64<1>(S, TW, tid);
    const float sc = mix * (1.0f/4096.0f);
    for (int k = tid; k < 4096; k += 512){
        int yy = k >> 6, xx = k & 63;
        float par = ((yy + xx) & 1) ? -sc : sc;  // ifftshift(h,w) -> output modulation
        o[k] = fmaf(par, S[SWA(yy, xx)].x, sp[k]);
    }
}

// ---------------- launch ----------------
extern "C" void kernel_launch(void* const* d_in, const int* in_sizes, int n_in,
                              void* d_out, int out_size){
    (void)in_sizes; (void)n_in; (void)out_size;
    const float* x      = (const float*)d_in[0];
    const float* f0     = (const float*)d_in[1];
    const float* theta  = (const float*)d_in[2];
    const float* sigma  = (const float*)d_in[3];
    const float* theta0 = (const float*)d_in[4];
    const float* fbs    = (const float*)d_in[5];
    const float* mix    = (const float*)d_in[6];
    const float* w1     = (const float*)d_in[7];
    const float* b1     = (const float*)d_in[8];
    const float* w2     = (const float*)d_in[9];
    const float* b2     = (const float*)d_in[10];
    const float* cw     = (const float*)d_in[11];
    float* out = (float*)d_out;

    k_fwd_fft<<<1536, 512>>>(x);
    k_attn<<<1024, 256>>>(f0, theta, sigma, theta0, w1, b1, w2, b2);
    k_conv<<<512, 256>>>(x, cw, mix);
    k_base<<<4096, 256>>>(out);
    k_inv<<<4096, 512>>>(fbs, mix, out);
}

// round 10
// speedup vs baseline: 3.0431x; 1.5977x over previous
#include <cuda_runtime.h>
#include <cuda_fp16.h>
#include <cstdint>

// ---------------- scratch (static device globals; no allocation) ----------------
__device__ __half2 g_XS2[64*32*32*64];   // complex spectrum fp16, [b][i-32][h-32][w]
__device__ float  g_AB [32*64*32*64];    // |xs| fp32, [p][c][h-32][w]
__device__ float  g_Wt [32*32*64];       // filter*attention weight [i-32][h-32][w]
__device__ float  g_xsp[64*64*64];       // (1-mix)*conv result [b][h][w]

// ---------------- reference swizzle (epilogues only; few uses) ----------------
__device__ __forceinline__ int SWA(int r, int c){
    int k = ((r & 6) ^ ((r >> 3) & 7)) ^ (((r ^ (r >> 3)) & 1) << 3);
    return (r << 6) + (c ^ ((c >> 3) & 7) ^ k);
}

// ---------------- packed f32x2 helpers (Blackwell) ----------------
__device__ __forceinline__ float2 cadd(float2 a, float2 b){
    float2 r;
    asm("add.rn.f32x2 %0, %1, %2;"
        : "=l"(reinterpret_cast<uint64_t&>(r))
        : "l"(reinterpret_cast<const uint64_t&>(a)),
          "l"(reinterpret_cast<const uint64_t&>(b)));
    return r;
}
__device__ __forceinline__ float2 csub(float2 a, float2 b){
    float2 r;
    asm("sub.rn.f32x2 %0, %1, %2;"
        : "=l"(reinterpret_cast<uint64_t&>(r))
        : "l"(reinterpret_cast<const uint64_t&>(a)),
          "l"(reinterpret_cast<const uint64_t&>(b)));
    return r;
}
__device__ __forceinline__ float2 ffma2(float2 a, float2 b, float2 c){
    float2 r;
    asm("fma.rn.f32x2 %0, %1, %2, %3;"
        : "=l"(reinterpret_cast<uint64_t&>(r))
        : "l"(reinterpret_cast<const uint64_t&>(a)),
          "l"(reinterpret_cast<const uint64_t&>(b)),
          "l"(reinterpret_cast<const uint64_t&>(c)));
    return r;
}

// ---------------- complex helpers ----------------
__device__ __forceinline__ float2 cmul(float2 a, float2 b){
    return make_float2(fmaf(a.x, b.x, -a.y*b.y), fmaf(a.x, b.y, a.y*b.x));
}

template<int DIR>
__device__ __forceinline__ float2 mulJ(float2 t){
    return (DIR < 0) ? make_float2(t.y, -t.x) : make_float2(-t.y, t.x);
}

template<int DIR>
__device__ __forceinline__ void fft8(float2 v[8]){
    float2 e0=v[0], e1=v[2], e2=v[4], e3=v[6];
    float2 o0=v[1], o1=v[3], o2=v[5], o3=v[7];
    float2 t0=cadd(e0,e2), t1=csub(e0,e2), t2=cadd(e1,e3), t3=mulJ<DIR>(csub(e1,e3));
    float2 E0=cadd(t0,t2), E1=cadd(t1,t3), E2=csub(t0,t2), E3=csub(t1,t3);
    float2 u0=cadd(o0,o2), u1=csub(o0,o2), u2=cadd(o1,o3), u3=mulJ<DIR>(csub(o1,o3));
    float2 O0=cadd(u0,u2), O1=cadd(u1,u3), O2=csub(u0,u2), O3=csub(u1,u3);
    const float s = 0.70710678118654752f;
    const float2 w1v = make_float2( s, DIR < 0 ? -s : s);
    const float2 w3v = make_float2(-s, DIR < 0 ? -s : s);
    O1 = cmul(O1, w1v);
    O2 = mulJ<DIR>(O2);
    O3 = cmul(O3, w3v);
    v[0]=cadd(E0,O0); v[4]=csub(E0,O0);
    v[1]=cadd(E1,O1); v[5]=csub(E1,O1);
    v[2]=cadd(E2,O2); v[6]=csub(E2,O2);
    v[3]=cadd(E3,O3); v[7]=csub(E3,O3);
}

// Full 2D 64x64 FFT, swizzled smem, strength-reduced addressing (1 XOR/access).
// Bit-identical layout to SWA(); algebra verified against it.
template<int DIR>
__device__ __forceinline__ void fft2d_64(float2* S, const float2* TW, int tid){
    const int t = tid & 7;
    const int line = tid >> 3;
    const int K  = ((line & 6) ^ ((line >> 3) & 7)) ^ (((line ^ (line >> 3)) & 1) << 3);
    char* Srow = (char*)S + (line << 9);
    const uint32_t TKB = (uint32_t)(t ^ K) << 3;
    const uint32_t UB  = (uint32_t)((t << 3) ^ t ^ K) << 3;
    float2 v[8];
    __syncthreads();
    // ---- rows: stage 1 (c = a*8+t; ld/st same address set) ----
    #pragma unroll
    for (int a=0;a<8;a++)
        v[a] = *(float2*)(Srow + ((uint32_t)(((a<<3)^a)<<3) ^ TKB));
    fft8<DIR>(v);
    #pragma unroll
    for (int c=0;c<8;c++)
        *(float2*)(Srow + ((uint32_t)(((c<<3)^c)<<3) ^ TKB)) = cmul(v[c], TW[t*c]);
    __syncthreads();
    // ---- rows: stage 2 (ld c = t*8+b; st c = d*8+t) ----
    #pragma unroll
    for (int b=0;b<8;b++)
        v[b] = *(float2*)(Srow + (UB ^ (uint32_t)(b<<3)));
    fft8<DIR>(v);
    __syncthreads();
    #pragma unroll
    for (int d=0;d<8;d++)
        *(float2*)(Srow + ((uint32_t)(((d<<3)^d)<<3) ^ TKB)) = v[d];
    __syncthreads();
    // ---- columns ----
    const int L = line ^ ((line >> 3) & 7);
    const uint32_t MB = (uint32_t)(L ^ (t & 6) ^ ((t & 1) << 3)) << 3;
    const uint32_t NB = (uint32_t)(L ^ t ^ ((t & 1) << 3)) << 3;
    char* Sb = (char*)S;
    const uint32_t TB9  = (uint32_t)t << 9;
    const uint32_t TB12 = (uint32_t)t << 12;
    // stage 1 (r = a*8+t; ld/st same set)
    #pragma unroll
    for (int a=0;a<8;a++)
        v[a] = *(float2*)(Sb + (uint32_t)(a<<12) + TB9 + (MB ^ (uint32_t)((a ^ ((a&1)<<3))<<3)));
    fft8<DIR>(v);
    #pragma unroll
    for (int c=0;c<8;c++)
        *(float2*)(Sb + (uint32_t)(c<<12) + TB9 + (MB ^ (uint32_t)((c ^ ((c&1)<<3))<<3))) = cmul(v[c], TW[t*c]);
    __syncthreads();
    // stage 2 (ld r = t*8+b; st r = d*8+t)
    #pragma unroll
    for (int b=0;b<8;b++)
        v[b] = *(float2*)(Sb + TB12 + (uint32_t)(b<<9) + (NB ^ (uint32_t)((((b&6) ^ ((b&1)<<3)))<<3)));
    fft8<DIR>(v);
    __syncthreads();
    #pragma unroll
    for (int d=0;d<8;d++)
        *(float2*)(Sb + (uint32_t)(d<<12) + TB9 + (MB ^ (uint32_t)((d ^ ((d&1)<<3))<<3))) = v[d];
    __syncthreads();
}

__device__ __forceinline__ int band_idx(float f){
    return (int)floorf((f + 1.0f) * 0.5f * 64.0f);
}

// ---------------- kernel A: forward FFT, paired real planes + activity pruning ----------------
__global__ __launch_bounds__(512) void k_fwd_fft(const float* __restrict__ x,
                                                 const float* __restrict__ fbs){
    __shared__ float2 S[64*64];
    __shared__ float2 TW[64];
    const int bx = blockIdx.x;
    const int tid = threadIdx.x;
    int pA, qA, pB, qB;
    bool magN, cA = false, cB = false;
    if (bx < 1024){                 // set1: q<32, pairs along p
        int q = bx & 31, m = bx >> 5;
        pA = 2*m;   pB = 2*m + 1;  qA = q; qB = q;
        magN = (pA < 32);
        const int i = q + 32;
        const int bA = (pA + 32) & 63, bB = (pB + 32) & 63;
        cA = (i >= band_idx(fbs[bA*2+0])) && (i < band_idx(fbs[bA*2+1]));
        cB = (i >= band_idx(fbs[bB*2+0])) && (i < band_idx(fbs[bB*2+1]));
        if (!magN && !cA && !cB) return;   // plane pair feeds nothing
    } else {                        // set2: p<32, q>=32, pairs along q (mag only)
        int idx = bx - 1024;
        int p = idx & 31, m = idx >> 5;
        pA = p; pB = p; qA = 32 + 2*m; qB = 33 + 2*m;
        magN = true;
    }
    if (tid < 64){
        float sn, cs;
        sincospif(-(float)tid * (1.0f/32.0f), &sn, &cs);
        TW[tid] = make_float2(cs, sn);
    }
    const float4* srcA = (const float4*)(x + ((size_t)(pA*64 + qA) << 12));
    const float4* srcB = (const float4*)(x + ((size_t)(pB*64 + qB) << 12));
    for (int k = tid; k < 1024; k += 512){
        float4 va = srcA[k];
        float4 vb = srcB[k];
        const int hh = k >> 4;
        const int w0 = (k & 15) * 4;
        float s0 = ((hh + w0) & 1) ? -1.0f : 1.0f;   // (-1)^(h+w) = fftshift(h,w)
        S[SWA(hh, w0+0)] = make_float2( va.x*s0,  vb.x*s0);
        S[SWA(hh, w0+1)] = make_float2(-va.y*s0, -vb.y*s0);
        S[SWA(hh, w0+2)] = make_float2( va.z*s0,  vb.z*s0);
        S[SWA(hh, w0+3)] = make_float2(-va.w*s0, -vb.w*s0);
    }
    fft2d_64<-1>(S, TW, tid);

    if (bx < 1024){
        const int bA = (pA + 32) & 63, bB = (pB + 32) & 63;
        __half2* dstA = g_XS2 + ((size_t)(bA*32 + qA) << 11);
        __half2* dstB = g_XS2 + ((size_t)(bB*32 + qB) << 11);
        float* magA = g_AB + ((size_t)(pA*64 + (qA + 32)) << 11);
        float* magB = g_AB + ((size_t)(pB*64 + (qB + 32)) << 11);
        for (int k = tid; k < 2048; k += 512){
            const int hh = 32 + (k >> 6);
            const int ww = k & 63;
            const int mh = 64 - hh;
            const int mw = (64 - ww) & 63;
            float2 z  = S[SWA(hh, ww)];
            float2 zp = S[SWA(mh, mw)];
            float2 fa = make_float2(0.5f*(z.x + zp.x), 0.5f*(z.y - zp.y));
            float2 fb = make_float2(0.5f*(z.y + zp.y), 0.5f*(zp.x - z.x));
            if (cA) dstA[k] = __floats2half2_rn(fa.x, fa.y);
            if (cB) dstB[k] = __floats2half2_rn(fb.x, fb.y);
            if (magN){
                magA[k] = sqrtf(fmaf(fa.x, fa.x, fa.y*fa.y));
                magB[k] = sqrtf(fmaf(fb.x, fb.x, fb.y*fb.y));
            }
        }
    } else {
        float* magA = g_AB + ((size_t)(pA*64 + (qA - 32)) << 11);
        float* magB = g_AB + ((size_t)(pB*64 + (qB - 32)) << 11);
        for (int k = tid; k < 2048; k += 512){
            const int hh = 32 + (k >> 6);
            const int ww = k & 63;
            const int mh = 64 - hh;
            const int mw = (64 - ww) & 63;
            float2 z  = S[SWA(hh, ww)];
            float2 zp = S[SWA(mh, mw)];
            float ax = 0.5f*(z.x + zp.x), ay = 0.5f*(z.y - zp.y);
            float bx2 = 0.5f*(z.y + zp.y), by = 0.5f*(zp.x - z.x);
            magA[k] = sqrtf(fmaf(ax, ax, ay*ay));
            magB[k] = sqrtf(fmaf(bx2, bx2, by*by));
        }
    }
}

// ---------------- kernel B: attention matvec + log-Gabor -> Wt ----------------
__global__ __launch_bounds__(256) void k_attn(const float* __restrict__ f0,
        const float* __restrict__ theta, const float* __restrict__ sigma,
        const float* __restrict__ theta0, const float* __restrict__ w1,
        const float* __restrict__ b1, const float* __restrict__ w2,
        const float* __restrict__ b2){
    __shared__ float sA[64*64];   // |xs| tile [c][w]
    __shared__ float sW[64*65];   // w1 [o][c] padded; reused as h1 [o][w]
    const int io = blockIdx.x & 31, hp = blockIdx.x >> 5;
    const int i = io + 32, h = hp + 32;
    const int tid = threadIdx.x;

    for (int k = tid; k < 4096; k += 256){
        int o = k >> 6, c = k & 63;
        sW[o*65 + c] = w1[k];
    }
    const float* base = g_AB + (((size_t)io*64) << 11) + ((size_t)hp << 6);
    for (int k = tid; k < 4096; k += 256){
        int c = k >> 6, w = k & 63;
        sA[c*64 + w] = base[((size_t)c << 11) + w];
    }
    __syncthreads();

    const int tw = tid & 15, to = tid >> 4;
    const int o0 = to*4, w0 = tw*4;
    float acc[4][4];
    #pragma unroll
    for (int j=0;j<4;j++){
        float bv = b1[o0+j];
        #pragma unroll
        for (int l=0;l<4;l++) acc[j][l] = bv;
    }
    for (int c=0;c<64;c++){
        float4 av = *(const float4*)&sA[c*64 + w0];
        float wv[4];
        #pragma unroll
        for (int j=0;j<4;j++) wv[j] = sW[(o0+j)*65 + c];
        #pragma unroll
        for (int j=0;j<4;j++){
            acc[j][0] = fmaf(wv[j], av.x, acc[j][0]);
            acc[j][1] = fmaf(wv[j], av.y, acc[j][1]);
            acc[j][2] = fmaf(wv[j], av.z, acc[j][2]);
            acc[j][3] = fmaf(wv[j], av.w, acc[j][3]);
        }
    }
    __syncthreads();
    #pragma unroll
    for (int j=0;j<4;j++)
        #pragma unroll
        for (int l=0;l<4;l++)
            sW[(o0+j)*65 + (w0+l)] = fmaxf(acc[j][l], 0.0f);
    __syncthreads();

    if (tid < 64){
        const int w = tid;
        float lg[3];
        #pragma unroll
        for (int s3=0;s3<3;s3++){
            float a = b2[s3];
            for (int o=0;o<64;o++) a = fmaf(w2[s3*64+o], sW[o*65+w], a);
            lg[s3] = a;
        }
        float mx = fmaxf(lg[0], fmaxf(lg[1], lg[2]));
        float e0 = expf(lg[0]-mx), e1 = expf(lg[1]-mx), e2 = expf(lg[2]-mx);
        float inv = 1.0f/(e0+e1+e2);
        float awv[3] = {e0*inv, e1*inv, e2*inv};
        float yy = 2.0f*(float)h/63.0f - 1.0f;
        float xx = 2.0f*(float)w/63.0f - 1.0f;
        float r2 = fmaf(xx, xx, fmaf(yy, yy, 1e-6f));
        float lr = 0.5f*logf(r2);
        float phi = atan2f(yy, xx);
        float wt = 0.0f;
        #pragma unroll
        for (int s3=0;s3<3;s3++){
            float lf0 = logf(f0[s3*64+i]);
            float ls  = logf(sigma[s3*64+i]);
            float d1 = lr - lf0;
            float g  = expf(-(d1*d1)/(2.0f*ls*ls));
            float d2 = phi - theta[s3*64+i];
            float t0v = theta0[s3*64+i];
            float ang = expf(-(d2*d2)/(2.0f*t0v*t0v));
            wt = fmaf(g*ang, awv[s3], wt);
        }
        g_Wt[(io*32 + hp)*64 + w] = wt;
    }
}

// ---------------- kernel C: 3x3 conv, channel pairs in f32x2 lanes ----------------
__device__ __forceinline__ int ROT2(int w){ return ((w >> 2) | (w << 4)) & 63; }

__global__ __launch_bounds__(256) void k_conv(const float* __restrict__ x,
                                              const float* __restrict__ cw,
                                              const float* __restrict__ mixp){
    __shared__ float2 pl2[10*64];
    __shared__ float2 cwS[32*9];
    const int b = blockIdx.x >> 3;
    const int r0 = (blockIdx.x & 7) * 8;
    const int tid = threadIdx.x;
    for (int k = tid; k < 288; k += 256){
        int cp = k / 9, t = k - cp*9;
        cwS[k] = make_float2(cw[(2*cp)*9 + t], cw[(2*cp+1)*9 + t]);
    }
    const int r  = tid >> 5;
    const int w0 = (tid & 31) * 2;
    float2 acc[2];
    acc[0] = make_float2(0.f, 0.f); acc[1] = make_float2(0.f, 0.f);
    const float2 zero2 = make_float2(0.f, 0.f);
    const int srow = tid >> 4;
    const int scol = (tid & 15) * 4;
    for (int cp = 0; cp < 32; cp++){
        __syncthreads();
        const float* srcA = x + ((size_t)(b*64 + 2*cp) << 12);
        const float* srcB = srcA + 4096;
        if (srow < 10){
            int gr = r0 + srow - 1;
            float4 a4 = make_float4(0.f,0.f,0.f,0.f), b4 = a4;
            if (gr >= 0 && gr < 64){
                a4 = *(const float4*)&srcA[gr*64 + scol];
                b4 = *(const float4*)&srcB[gr*64 + scol];
            }
            pl2[srow*64 + ROT2(scol+0)] = make_float2(a4.x, b4.x);
            pl2[srow*64 + ROT2(scol+1)] = make_float2(a4.y, b4.y);
            pl2[srow*64 + ROT2(scol+2)] = make_float2(a4.z, b4.z);
            pl2[srow*64 + ROT2(scol+3)] = make_float2(a4.w, b4.w);
        }
        __syncthreads();
        float2 c9[9];
        #pragma unroll
        for (int q=0;q<9;q++) c9[q] = cwS[cp*9 + q];
        #pragma unroll
        for (int dy=0; dy<3; dy++){
            const float2* row = &pl2[(r+dy)*64];
            float2 m1 = (w0 > 0) ? row[ROT2(w0-1)] : zero2;
            float2 v0 = row[ROT2(w0)];
            float2 v1 = row[ROT2(w0+1)];
            float2 p2 = (w0+2 < 64) ? row[ROT2(w0+2)] : zero2;
            const float2* cr = &c9[dy*3];
            acc[0] = ffma2(cr[0], m1, acc[0]); acc[0] = ffma2(cr[1], v0, acc[0]); acc[0] = ffma2(cr[2], v1, acc[0]);
            acc[1] = ffma2(cr[0], v0, acc[1]); acc[1] = ffma2(cr[1], v1, acc[1]); acc[1] = ffma2(cr[2], p2, acc[1]);
        }
    }
    const float c1 = 1.0f - mixp[0];
    float* dst = g_xsp + b*4096 + (r0 + r)*64 + w0;
    dst[0] = c1 * (acc[0].x + acc[0].y);
    dst[1] = c1 * (acc[1].x + acc[1].y);
}

// ---------------- kernel D: merged output (copy OR masked IFFT + mix) ----------------
__global__ __launch_bounds__(512) void k_out(const float* __restrict__ fbs,
        const float* __restrict__ mixp, float* __restrict__ out){
    const int bo = blockIdx.x >> 6, ioo = blockIdx.x & 63;
    const int b = (bo + 32) & 63, i = (ioo + 32) & 63;   // ifftshift of batch/channel dims
    const int sidx = band_idx(fbs[b*2+0]);               // in [32,64)
    const int eidx = band_idx(fbs[b*2+1]);
    const int tid = threadIdx.x;
    float* o = out + ((size_t)blockIdx.x << 12);
    const float* sp = g_xsp + bo*4096;                   // already scaled by (1-mix)
    if (i < sidx || i >= eidx){
        // inactive plane: pure stream copy of base term
        const float4* sp4 = (const float4*)sp;
        float4* o4 = (float4*)o;
        o4[tid]       = sp4[tid];
        o4[tid + 512] = sp4[tid + 512];
        return;
    }
    __shared__ float2 S[64*64];
    __shared__ float2 TW[64];
    const float mix = mixp[0];
    if (tid < 64){
        float sn, cs;
        sincospif((float)tid * (1.0f/32.0f), &sn, &cs);
        TW[tid] = make_float2(cs, sn);
    }
    for (int k = tid; k < 4096; k += 512)
        S[k] = make_float2(0.0f, 0.0f);
    __syncthreads();
    {
        const int nrows = eidx - sidx;
        const __half2* src = g_XS2 + (((size_t)(b*32 + (i-32)) << 5) + (sidx - 32)) * 64;
        const float*   wr  = g_Wt + ((i-32)*32 + (sidx - 32))*64;
        for (int k = tid; k < nrows*64; k += 512){
            int rr = k >> 6, w = k & 63;
            float2 z = __half22float2(src[k]);
            float wv = wr[rr*64 + w];
            S[SWA(sidx + rr, w)] = make_float2(z.x*wv, z.y*wv);
        }
    }
    fft2d_64<1>(S, TW, tid);
    const float sc = mix * (1.0f/4096.0f);
    for (int k = tid; k < 4096; k += 512){
        int yy = k >> 6, xx = k & 63;
        float par = ((yy + xx) & 1) ? -sc : sc;          // ifftshift(h,w) modulation
        o[k] = fmaf(par, S[SWA(yy, xx)].x, sp[k]);
    }
}

// ---------------- launch ----------------
extern "C" void kernel_launch(void* const* d_in, const int* in_sizes, int n_in,
                              void* d_out, int out_size){
    (void)in_sizes; (void)n_in; (void)out_size;
    const float* x      = (const float*)d_in[0];
    const float* f0     = (const float*)d_in[1];
    const float* theta  = (const float*)d_in[2];
    const float* sigma  = (const float*)d_in[3];
    const float* theta0 = (const float*)d_in[4];
    const float* fbs    = (const float*)d_in[5];
    const float* mix    = (const float*)d_in[6];
    const float* w1     = (const float*)d_in[7];
    const float* b1     = (const float*)d_in[8];
    const float* w2     = (const float*)d_in[9];
    const float* b2     = (const float*)d_in[10];
    const float* cw     = (const float*)d_in[11];
    float* out = (float*)d_out;

    k_fwd_fft<<<1536, 512>>>(x, fbs);
    k_attn<<<1024, 256>>>(f0, theta, sigma, theta0, w1, b1, w2, b2);
    k_conv<<<512, 256>>>(x, cw, mix);
    k_out<<<4096, 512>>>(fbs, mix, out);
}

// round 11
// speedup vs baseline: 3.2472x; 1.0671x over previous
#include <cuda_runtime.h>
#include <cuda_fp16.h>
#include <cstdint>

// ---------------- scratch (static device globals; no allocation) ----------------
__device__ __half2 g_XS2[64*32*32*64];   // complex spectrum fp16, [b][i-32][h-32][w]
__device__ float  g_AB [32*64*32*64];    // |xs| fp32, [p][c][h-32][w]
__device__ float  g_Wt [32*32*64];       // filter*attention weight [i-32][h-32][w]
__device__ float  g_xsp[64*64*64];       // (1-mix)*conv result [b][h][w]

// ---------------- reference swizzle (epilogues only; few uses) ----------------
__device__ __forceinline__ int SWA(int r, int c){
    int k = ((r & 6) ^ ((r >> 3) & 7)) ^ (((r ^ (r >> 3)) & 1) << 3);
    return (r << 6) + (c ^ ((c >> 3) & 7) ^ k);
}

// ---------------- packed f32x2 helpers (Blackwell) ----------------
__device__ __forceinline__ float2 cadd(float2 a, float2 b){
    float2 r;
    asm("add.rn.f32x2 %0, %1, %2;"
        : "=l"(reinterpret_cast<uint64_t&>(r))
        : "l"(reinterpret_cast<const uint64_t&>(a)),
          "l"(reinterpret_cast<const uint64_t&>(b)));
    return r;
}
__device__ __forceinline__ float2 csub(float2 a, float2 b){
    float2 r;
    asm("sub.rn.f32x2 %0, %1, %2;"
        : "=l"(reinterpret_cast<uint64_t&>(r))
        : "l"(reinterpret_cast<const uint64_t&>(a)),
          "l"(reinterpret_cast<const uint64_t&>(b)));
    return r;
}
__device__ __forceinline__ float2 ffma2(float2 a, float2 b, float2 c){
    float2 r;
    asm("fma.rn.f32x2 %0, %1, %2, %3;"
        : "=l"(reinterpret_cast<uint64_t&>(r))
        : "l"(reinterpret_cast<const uint64_t&>(a)),
          "l"(reinterpret_cast<const uint64_t&>(b)),
          "l"(reinterpret_cast<const uint64_t&>(c)));
    return r;
}

// ---------------- complex helpers ----------------
__device__ __forceinline__ float2 cmul(float2 a, float2 b){
    return make_float2(fmaf(a.x, b.x, -a.y*b.y), fmaf(a.x, b.y, a.y*b.x));
}

template<int DIR>
__device__ __forceinline__ float2 mulJ(float2 t){
    return (DIR < 0) ? make_float2(t.y, -t.x) : make_float2(-t.y, t.x);
}

template<int DIR>
__device__ __forceinline__ void fft8(float2 v[8]){
    float2 e0=v[0], e1=v[2], e2=v[4], e3=v[6];
    float2 o0=v[1], o1=v[3], o2=v[5], o3=v[7];
    float2 t0=cadd(e0,e2), t1=csub(e0,e2), t2=cadd(e1,e3), t3=mulJ<DIR>(csub(e1,e3));
    float2 E0=cadd(t0,t2), E1=cadd(t1,t3), E2=csub(t0,t2), E3=csub(t1,t3);
    float2 u0=cadd(o0,o2), u1=csub(o0,o2), u2=cadd(o1,o3), u3=mulJ<DIR>(csub(o1,o3));
    float2 O0=cadd(u0,u2), O1=cadd(u1,u3), O2=csub(u0,u2), O3=csub(u1,u3);
    const float s = 0.70710678118654752f;
    const float2 w1v = make_float2( s, DIR < 0 ? -s : s);
    const float2 w3v = make_float2(-s, DIR < 0 ? -s : s);
    O1 = cmul(O1, w1v);
    O2 = mulJ<DIR>(O2);
    O3 = cmul(O3, w3v);
    v[0]=cadd(E0,O0); v[4]=csub(E0,O0);
    v[1]=cadd(E1,O1); v[5]=csub(E1,O1);
    v[2]=cadd(E2,O2); v[6]=csub(E2,O2);
    v[3]=cadd(E3,O3); v[7]=csub(E3,O3);
}

// Full 2D 64x64 FFT, swizzled smem, strength-reduced addressing.
// Intra-dimension hazards are same-warp (8 aligned threads own each line/column)
// -> __syncwarp(); only the transpose boundary and entry/exit need full barriers.
template<int DIR>
__device__ __forceinline__ void fft2d_64(float2* S, const float2* TW, int tid){
    const int t = tid & 7;
    const int line = tid >> 3;
    const int K  = ((line & 6) ^ ((line >> 3) & 7)) ^ (((line ^ (line >> 3)) & 1) << 3);
    char* Srow = (char*)S + (line << 9);
    const uint32_t TKB = (uint32_t)(t ^ K) << 3;
    const uint32_t UB  = (uint32_t)((t << 3) ^ t ^ K) << 3;
    float2 v[8];
    __syncthreads();
    // ---- rows: stage 1 (c = a*8+t; ld/st same address set) ----
    #pragma unroll
    for (int a=0;a<8;a++)
        v[a] = *(float2*)(Srow + ((uint32_t)(((a<<3)^a)<<3) ^ TKB));
    fft8<DIR>(v);
    #pragma unroll
    for (int c=0;c<8;c++)
        *(float2*)(Srow + ((uint32_t)(((c<<3)^c)<<3) ^ TKB)) = cmul(v[c], TW[t*c]);
    __syncwarp();
    // ---- rows: stage 2 (ld c = t*8+b; st c = d*8+t) — same line, same warp ----
    #pragma unroll
    for (int b=0;b<8;b++)
        v[b] = *(float2*)(Srow + (UB ^ (uint32_t)(b<<3)));
    fft8<DIR>(v);
    __syncwarp();
    #pragma unroll
    for (int d=0;d<8;d++)
        *(float2*)(Srow + ((uint32_t)(((d<<3)^d)<<3) ^ TKB)) = v[d];
    __syncthreads();            // transpose boundary (cross-warp)
    // ---- columns ----
    const int L = line ^ ((line >> 3) & 7);
    const uint32_t MB = (uint32_t)(L ^ (t & 6) ^ ((t & 1) << 3)) << 3;
    const uint32_t NB = (uint32_t)(L ^ t ^ ((t & 1) << 3)) << 3;
    char* Sb = (char*)S;
    const uint32_t TB9  = (uint32_t)t << 9;
    const uint32_t TB12 = (uint32_t)t << 12;
    // stage 1 (r = a*8+t; ld/st same set)
    #pragma unroll
    for (int a=0;a<8;a++)
        v[a] = *(float2*)(Sb + (uint32_t)(a<<12) + TB9 + (MB ^ (uint32_t)((a ^ ((a&1)<<3))<<3)));
    fft8<DIR>(v);
    #pragma unroll
    for (int c=0;c<8;c++)
        *(float2*)(Sb + (uint32_t)(c<<12) + TB9 + (MB ^ (uint32_t)((c ^ ((c&1)<<3))<<3))) = cmul(v[c], TW[t*c]);
    __syncwarp();
    // stage 2 (ld r = t*8+b; st r = d*8+t) — same column, same warp
    #pragma unroll
    for (int b=0;b<8;b++)
        v[b] = *(float2*)(Sb + TB12 + (uint32_t)(b<<9) + (NB ^ (uint32_t)((((b&6) ^ ((b&1)<<3)))<<3)));
    fft8<DIR>(v);
    __syncwarp();
    #pragma unroll
    for (int d=0;d<8;d++)
        *(float2*)(Sb + (uint32_t)(d<<12) + TB9 + (MB ^ (uint32_t)((d ^ ((d&1)<<3))<<3))) = v[d];
    __syncthreads();            // before cross-warp epilogue reads
}

__device__ __forceinline__ int band_idx(float f){
    return (int)floorf((f + 1.0f) * 0.5f * 64.0f);
}

__device__ __forceinline__ int ROT2(int w){ return ((w >> 2) | (w << 4)) & 63; }

// ---------------- kernel A: conv blocks (front) + forward FFT blocks ----------------
// Grid: [0,256)   -> 3x3 conv (batch b = bx>>2, 16-row tile)
//       [256,1792)-> forward FFT with plane pairing + activity pruning
__global__ __launch_bounds__(512) void k_fwdconv(const float* __restrict__ x,
                                                 const float* __restrict__ fbs,
                                                 const float* __restrict__ cw,
                                                 const float* __restrict__ mixp){
    __shared__ float2 S[64*64];
    __shared__ float2 TW[64];
    const int tid = threadIdx.x;

    if (blockIdx.x < 256){
        // ======== 3x3 spatial conv, channel pairs in f32x2 lanes ========
        float2* pl2 = S;                 // [18][64] rot2-swizzled
        float2* cwS = S + 18*64;         // [32][9]
        const int cbx = blockIdx.x;
        const int b = cbx >> 2;
        const int r0 = (cbx & 3) * 16;
        for (int k = tid; k < 288; k += 512){
            int cp = k / 9, t = k - cp*9;
            cwS[k] = make_float2(cw[(2*cp)*9 + t], cw[(2*cp+1)*9 + t]);
        }
        const int r  = tid >> 5;          // 0..15
        const int w0 = (tid & 31) * 2;    // 0..62
        float2 acc[2];
        acc[0] = make_float2(0.f, 0.f); acc[1] = make_float2(0.f, 0.f);
        const float2 zero2 = make_float2(0.f, 0.f);
        const int srow = tid >> 4;        // 0..31 (use <18)
        const int scol = (tid & 15) * 4;
        for (int cp = 0; cp < 32; cp++){
            __syncthreads();
            const float* srcA = x + ((size_t)(b*64 + 2*cp) << 12);
            const float* srcB = srcA + 4096;
            if (srow < 18){
                int gr = r0 + srow - 1;
                float4 a4 = make_float4(0.f,0.f,0.f,0.f), b4 = a4;
                if (gr >= 0 && gr < 64){
                    a4 = *(const float4*)&srcA[gr*64 + scol];
                    b4 = *(const float4*)&srcB[gr*64 + scol];
                }
                pl2[srow*64 + ROT2(scol+0)] = make_float2(a4.x, b4.x);
                pl2[srow*64 + ROT2(scol+1)] = make_float2(a4.y, b4.y);
                pl2[srow*64 + ROT2(scol+2)] = make_float2(a4.z, b4.z);
                pl2[srow*64 + ROT2(scol+3)] = make_float2(a4.w, b4.w);
            }
            __syncthreads();
            float2 c9[9];
            #pragma unroll
            for (int q=0;q<9;q++) c9[q] = cwS[cp*9 + q];
            #pragma unroll
            for (int dy=0; dy<3; dy++){
                const float2* row = &pl2[(r+dy)*64];
                float2 m1 = (w0 > 0) ? row[ROT2(w0-1)] : zero2;
                float2 v0 = row[ROT2(w0)];
                float2 v1 = row[ROT2(w0+1)];
                float2 p2 = (w0+2 < 64) ? row[ROT2(w0+2)] : zero2;
                const float2* cr = &c9[dy*3];
                acc[0] = ffma2(cr[0], m1, acc[0]); acc[0] = ffma2(cr[1], v0, acc[0]); acc[0] = ffma2(cr[2], v1, acc[0]);
                acc[1] = ffma2(cr[0], v0, acc[1]); acc[1] = ffma2(cr[1], v1, acc[1]); acc[1] = ffma2(cr[2], p2, acc[1]);
            }
        }
        const float c1 = 1.0f - mixp[0];
        float* dst = g_xsp + b*4096 + (r0 + r)*64 + w0;
        dst[0] = c1 * (acc[0].x + acc[0].y);
        dst[1] = c1 * (acc[1].x + acc[1].y);
        return;
    }

    // ======== forward FFT ========
    const int bx = blockIdx.x - 256;      // 0..1535
    int pA, qA, pB, qB;
    bool magN, cA = false, cB = false;
    if (bx < 1024){                 // set1: q<32, pairs along p
        int q = bx & 31, m = bx >> 5;
        pA = 2*m;   pB = 2*m + 1;  qA = q; qB = q;
        magN = (pA < 32);
        const int i = q + 32;
        const int bA = (pA + 32) & 63, bB = (pB + 32) & 63;
        cA = (i >= band_idx(fbs[bA*2+0])) && (i < band_idx(fbs[bA*2+1]));
        cB = (i >= band_idx(fbs[bB*2+0])) && (i < band_idx(fbs[bB*2+1]));
        if (!magN && !cA && !cB) return;   // plane pair feeds nothing
    } else {                        // set2: p<32, q>=32, pairs along q (mag only)
        int idx = bx - 1024;
        int p = idx & 31, m = idx >> 5;
        pA = p; pB = p; qA = 32 + 2*m; qB = 33 + 2*m;
        magN = true;
    }
    if (tid < 64){
        float sn, cs;
        sincospif(-(float)tid * (1.0f/32.0f), &sn, &cs);
        TW[tid] = make_float2(cs, sn);
    }
    const float4* srcA = (const float4*)(x + ((size_t)(pA*64 + qA) << 12));
    const float4* srcB = (const float4*)(x + ((size_t)(pB*64 + qB) << 12));
    for (int k = tid; k < 1024; k += 512){
        float4 va = srcA[k];
        float4 vb = srcB[k];
        const int hh = k >> 4;
        const int w0 = (k & 15) * 4;
        float s0 = ((hh + w0) & 1) ? -1.0f : 1.0f;   // (-1)^(h+w) = fftshift(h,w)
        S[SWA(hh, w0+0)] = make_float2( va.x*s0,  vb.x*s0);
        S[SWA(hh, w0+1)] = make_float2(-va.y*s0, -vb.y*s0);
        S[SWA(hh, w0+2)] = make_float2( va.z*s0,  vb.z*s0);
        S[SWA(hh, w0+3)] = make_float2(-va.w*s0, -vb.w*s0);
    }
    fft2d_64<-1>(S, TW, tid);

    if (bx < 1024){
        const int bA = (pA + 32) & 63, bB = (pB + 32) & 63;
        __half2* dstA = g_XS2 + ((size_t)(bA*32 + qA) << 11);
        __half2* dstB = g_XS2 + ((size_t)(bB*32 + qB) << 11);
        float* magA = g_AB + ((size_t)(pA*64 + (qA + 32)) << 11);
        float* magB = g_AB + ((size_t)(pB*64 + (qB + 32)) << 11);
        for (int k = tid; k < 2048; k += 512){
            const int hh = 32 + (k >> 6);
            const int ww = k & 63;
            const int mh = 64 - hh;
            const int mw = (64 - ww) & 63;
            float2 z  = S[SWA(hh, ww)];
            float2 zp = S[SWA(mh, mw)];
            float2 fa = make_float2(0.5f*(z.x + zp.x), 0.5f*(z.y - zp.y));
            float2 fb = make_float2(0.5f*(z.y + zp.y), 0.5f*(zp.x - z.x));
            if (cA) dstA[k] = __floats2half2_rn(fa.x, fa.y);
            if (cB) dstB[k] = __floats2half2_rn(fb.x, fb.y);
            if (magN){
                magA[k] = sqrtf(fmaf(fa.x, fa.x, fa.y*fa.y));
                magB[k] = sqrtf(fmaf(fb.x, fb.x, fb.y*fb.y));
            }
        }
    } else {
        float* magA = g_AB + ((size_t)(pA*64 + (qA - 32)) << 11);
        float* magB = g_AB + ((size_t)(pB*64 + (qB - 32)) << 11);
        for (int k = tid; k < 2048; k += 512){
            const int hh = 32 + (k >> 6);
            const int ww = k & 63;
            const int mh = 64 - hh;
            const int mw = (64 - ww) & 63;
            float2 z  = S[SWA(hh, ww)];
            float2 zp = S[SWA(mh, mw)];
            float ax = 0.5f*(z.x + zp.x), ay = 0.5f*(z.y - zp.y);
            float bx2 = 0.5f*(z.y + zp.y), by = 0.5f*(zp.x - z.x);
            magA[k] = sqrtf(fmaf(ax, ax, ay*ay));
            magB[k] = sqrtf(fmaf(bx2, bx2, by*by));
        }
    }
}

// ---------------- kernel B: attention matvec + log-Gabor -> Wt ----------------
__global__ __launch_bounds__(256) void k_attn(const float* __restrict__ f0,
        const float* __restrict__ theta, const float* __restrict__ sigma,
        const float* __restrict__ theta0, const float* __restrict__ w1,
        const float* __restrict__ b1, const float* __restrict__ w2,
        const float* __restrict__ b2){
    __shared__ float sA[64*64];   // |xs| tile [c][w]
    __shared__ float sW[64*65];   // w1 [o][c] padded; reused as h1 [o][w]
    const int io = blockIdx.x & 31, hp = blockIdx.x >> 5;
    const int i = io + 32, h = hp + 32;
    const int tid = threadIdx.x;

    for (int k = tid; k < 4096; k += 256){
        int o = k >> 6, c = k & 63;
        sW[o*65 + c] = w1[k];
    }
    const float* base = g_AB + (((size_t)io*64) << 11) + ((size_t)hp << 6);
    for (int k = tid; k < 4096; k += 256){
        int c = k >> 6, w = k & 63;
        sA[c*64 + w] = base[((size_t)c << 11) + w];
    }
    __syncthreads();

    const int tw = tid & 15, to = tid >> 4;
    const int o0 = to*4, w0 = tw*4;
    float acc[4][4];
    #pragma unroll
    for (int j=0;j<4;j++){
        float bv = b1[o0+j];
        #pragma unroll
        for (int l=0;l<4;l++) acc[j][l] = bv;
    }
    for (int c=0;c<64;c++){
        float4 av = *(const float4*)&sA[c*64 + w0];
        float wv[4];
        #pragma unroll
        for (int j=0;j<4;j++) wv[j] = sW[(o0+j)*65 + c];
        #pragma unroll
        for (int j=0;j<4;j++){
            acc[j][0] = fmaf(wv[j], av.x, acc[j][0]);
            acc[j][1] = fmaf(wv[j], av.y, acc[j][1]);
            acc[j][2] = fmaf(wv[j], av.z, acc[j][2]);
            acc[j][3] = fmaf(wv[j], av.w, acc[j][3]);
        }
    }
    __syncthreads();
    #pragma unroll
    for (int j=0;j<4;j++)
        #pragma unroll
        for (int l=0;l<4;l++)
            sW[(o0+j)*65 + (w0+l)] = fmaxf(acc[j][l], 0.0f);
    __syncthreads();

    if (tid < 64){
        const int w = tid;
        float lg[3];
        #pragma unroll
        for (int s3=0;s3<3;s3++){
            float a = b2[s3];
            for (int o=0;o<64;o++) a = fmaf(w2[s3*64+o], sW[o*65+w], a);
            lg[s3] = a;
        }
        float mx = fmaxf(lg[0], fmaxf(lg[1], lg[2]));
        float e0 = expf(lg[0]-mx), e1 = expf(lg[1]-mx), e2 = expf(lg[2]-mx);
        float inv = 1.0f/(e0+e1+e2);
        float awv[3] = {e0*inv, e1*inv, e2*inv};
        float yy = 2.0f*(float)h/63.0f - 1.0f;
        float xx = 2.0f*(float)w/63.0f - 1.0f;
        float r2 = fmaf(xx, xx, fmaf(yy, yy, 1e-6f));
        float lr = 0.5f*logf(r2);
        float phi = atan2f(yy, xx);
        float wt = 0.0f;
        #pragma unroll
        for (int s3=0;s3<3;s3++){
            float lf0 = logf(f0[s3*64+i]);
            float ls  = logf(sigma[s3*64+i]);
            float d1 = lr - lf0;
            float g  = expf(-(d1*d1)/(2.0f*ls*ls));
            float d2 = phi - theta[s3*64+i];
            float t0v = theta0[s3*64+i];
            float ang = expf(-(d2*d2)/(2.0f*t0v*t0v));
            wt = fmaf(g*ang, awv[s3], wt);
        }
        g_Wt[(io*32 + hp)*64 + w] = wt;
    }
}

// ---------------- kernel D: merged output (copy OR masked IFFT + mix) ----------------
__global__ __launch_bounds__(512) void k_out(const float* __restrict__ fbs,
        const float* __restrict__ mixp, float* __restrict__ out){
    const int bo = blockIdx.x >> 6, ioo = blockIdx.x & 63;
    const int b = (bo + 32) & 63, i = (ioo + 32) & 63;   // ifftshift of batch/channel dims
    const int sidx = band_idx(fbs[b*2+0]);               // in [32,64)
    const int eidx = band_idx(fbs[b*2+1]);
    const int tid = threadIdx.x;
    float* o = out + ((size_t)blockIdx.x << 12);
    const float* sp = g_xsp + bo*4096;                   // already scaled by (1-mix)
    if (i < sidx || i >= eidx){
        // inactive plane: pure stream copy of base term
        const float4* sp4 = (const float4*)sp;
        float4* o4 = (float4*)o;
        o4[tid]       = sp4[tid];
        o4[tid + 512] = sp4[tid + 512];
        return;
    }
    __shared__ float2 S[64*64];
    __shared__ float2 TW[64];
    const float mix = mixp[0];
    if (tid < 64){
        float sn, cs;
        sincospif((float)tid * (1.0f/32.0f), &sn, &cs);
        TW[tid] = make_float2(cs, sn);
    }
    for (int k = tid; k < 4096; k += 512)
        S[k] = make_float2(0.0f, 0.0f);
    __syncthreads();
    {
        const int nrows = eidx - sidx;
        const __half2* src = g_XS2 + (((size_t)(b*32 + (i-32)) << 5) + (sidx - 32)) * 64;
        const float*   wr  = g_Wt + ((i-32)*32 + (sidx - 32))*64;
        for (int k = tid; k < nrows*64; k += 512){
            int rr = k >> 6, w = k & 63;
            float2 z = __half22float2(src[k]);
            float wv = wr[rr*64 + w];
            S[SWA(sidx + rr, w)] = make_float2(z.x*wv, z.y*wv);
        }
    }
    fft2d_64<1>(S, TW, tid);
    const float sc = mix * (1.0f/4096.0f);
    for (int k = tid; k < 4096; k += 512){
        int yy = k >> 6, xx = k & 63;
        float par = ((yy + xx) & 1) ? -sc : sc;          // ifftshift(h,w) modulation
        o[k] = fmaf(par, S[SWA(yy, xx)].x, sp[k]);
    }
}

// ---------------- launch ----------------
extern "C" void kernel_launch(void* const* d_in, const int* in_sizes, int n_in,
                              void* d_out, int out_size){
    (void)in_sizes; (void)n_in; (void)out_size;
    const float* x      = (const float*)d_in[0];
    const float* f0     = (const float*)d_in[1];
    const float* theta  = (const float*)d_in[2];
    const float* sigma  = (const float*)d_in[3];
    const float* theta0 = (const float*)d_in[4];
    const float* fbs    = (const float*)d_in[5];
    const float* mix    = (const float*)d_in[6];
    const float* w1     = (const float*)d_in[7];
    const float* b1     = (const float*)d_in[8];
    const float* w2     = (const float*)d_in[9];
    const float* b2     = (const float*)d_in[10];
    const float* cw     = (const float*)d_in[11];
    float* out = (float*)d_out;

    k_fwdconv<<<1792, 512>>>(x, fbs, cw, mix);
    k_attn<<<1024, 256>>>(f0, theta, sigma, theta0, w1, b1, w2, b2);
    k_out<<<4096, 512>>>(fbs, mix, out);
}

// round 12
// speedup vs baseline: 3.3542x; 1.0330x over previous
#include <cuda_runtime.h>
#include <cuda_fp16.h>
#include <cstdint>

// ---------------- scratch (static device globals; no allocation) ----------------
__device__ __half2 g_XS2[64*32*32*64];   // complex spectrum fp16, [b][i-32][h-32][w]
__device__ float  g_AB [32*64*32*64];    // |xs| fp32, [p][c][h-32][w]
__device__ float  g_Wt [32*32*64];       // filter*attention weight [i-32][h-32][w]
__device__ float  g_xsp[64*64*64];       // (1-mix)*conv result [b][h][w]

// ---------------- reference swizzle (epilogues only) ----------------
__device__ __forceinline__ int SWA(int r, int c){
    int k = ((r & 6) ^ ((r >> 3) & 7)) ^ (((r ^ (r >> 3)) & 1) << 3);
    return (r << 6) + (c ^ ((c >> 3) & 7) ^ k);
}

// ---------------- packed f32x2 helpers (Blackwell) ----------------
__device__ __forceinline__ float2 cadd(float2 a, float2 b){
    float2 r;
    asm("add.rn.f32x2 %0, %1, %2;"
        : "=l"(reinterpret_cast<uint64_t&>(r))
        : "l"(reinterpret_cast<const uint64_t&>(a)),
          "l"(reinterpret_cast<const uint64_t&>(b)));
    return r;
}
__device__ __forceinline__ float2 csub(float2 a, float2 b){
    float2 r;
    asm("sub.rn.f32x2 %0, %1, %2;"
        : "=l"(reinterpret_cast<uint64_t&>(r))
        : "l"(reinterpret_cast<const uint64_t&>(a)),
          "l"(reinterpret_cast<const uint64_t&>(b)));
    return r;
}
__device__ __forceinline__ float2 ffma2(float2 a, float2 b, float2 c){
    float2 r;
    asm("fma.rn.f32x2 %0, %1, %2, %3;"
        : "=l"(reinterpret_cast<uint64_t&>(r))
        : "l"(reinterpret_cast<const uint64_t&>(a)),
          "l"(reinterpret_cast<const uint64_t&>(b)),
          "l"(reinterpret_cast<const uint64_t&>(c)));
    return r;
}

__device__ __forceinline__ float2 cmul(float2 a, float2 b){
    return make_float2(fmaf(a.x, b.x, -a.y*b.y), fmaf(a.x, b.y, a.y*b.x));
}

template<int DIR>
__device__ __forceinline__ float2 mulJ(float2 t){
    return (DIR < 0) ? make_float2(t.y, -t.x) : make_float2(-t.y, t.x);
}

template<int DIR>
__device__ __forceinline__ void fft8(float2 v[8]){
    float2 e0=v[0], e1=v[2], e2=v[4], e3=v[6];
    float2 o0=v[1], o1=v[3], o2=v[5], o3=v[7];
    float2 t0=cadd(e0,e2), t1=csub(e0,e2), t2=cadd(e1,e3), t3=mulJ<DIR>(csub(e1,e3));
    float2 E0=cadd(t0,t2), E1=cadd(t1,t3), E2=csub(t0,t2), E3=csub(t1,t3);
    float2 u0=cadd(o0,o2), u1=csub(o0,o2), u2=cadd(o1,o3), u3=mulJ<DIR>(csub(o1,o3));
    float2 O0=cadd(u0,u2), O1=cadd(u1,u3), O2=csub(u0,u2), O3=csub(u1,u3);
    const float s = 0.70710678118654752f;
    const float2 w1v = make_float2( s, DIR < 0 ? -s : s);
    const float2 w3v = make_float2(-s, DIR < 0 ? -s : s);
    O1 = cmul(O1, w1v);
    O2 = mulJ<DIR>(O2);
    O3 = cmul(O3, w3v);
    v[0]=cadd(E0,O0); v[4]=csub(E0,O0);
    v[1]=cadd(E1,O1); v[5]=csub(E1,O1);
    v[2]=cadd(E2,O2); v[6]=csub(E2,O2);
    v[3]=cadd(E3,O3); v[7]=csub(E3,O3);
}

// Per-thread twiddles w8[c] = e^{DIR*2*pi*i*t*c/64}.
template<int DIR>
__device__ __forceinline__ void make_tw(float2 w8[8], int t){
    float sn, cs;
    sincospif((DIR < 0 ? -(float)t : (float)t) * (1.0f/32.0f), &sn, &cs);
    w8[0] = make_float2(1.0f, 0.0f);
    w8[1] = make_float2(cs, sn);
    #pragma unroll
    for (int c = 2; c < 8; c++) w8[c] = cmul(w8[c-1], w8[1]);
}

// Row stage-1 store (with twiddle), then remaining 3 FFT stages.
// Caller provides v[] = fft8 of row `line` samples (cols a*8+t), and w8.
template<int DIR>
__device__ __forceinline__ void fft2d_from_rows(float2* S, float2 v[8],
                                                const float2 w8[8], int tid){
    const int t = tid & 7;
    const int line = tid >> 3;
    const int K  = ((line & 6) ^ ((line >> 3) & 7)) ^ (((line ^ (line >> 3)) & 1) << 3);
    char* Srow = (char*)S + (line << 9);
    const uint32_t TKB = (uint32_t)(t ^ K) << 3;
    const uint32_t UB  = (uint32_t)((t << 3) ^ t ^ K) << 3;
    // rows stage-1 store (twiddled)
    *(float2*)(Srow + (0u ^ TKB)) = v[0];
    #pragma unroll
    for (int c=1;c<8;c++)
        *(float2*)(Srow + ((uint32_t)(((c<<3)^c)<<3) ^ TKB)) = cmul(v[c], w8[c]);
    __syncwarp();
    // rows stage-2 (same line -> same warp)
    #pragma unroll
    for (int b=0;b<8;b++)
        v[b] = *(float2*)(Srow + (UB ^ (uint32_t)(b<<3)));
    fft8<DIR>(v);
    __syncwarp();
    #pragma unroll
    for (int d=0;d<8;d++)
        *(float2*)(Srow + ((uint32_t)(((d<<3)^d)<<3) ^ TKB)) = v[d];
    __syncthreads();            // transpose boundary (cross-warp)
    // columns
    const int L = line ^ ((line >> 3) & 7);
    const uint32_t MB = (uint32_t)(L ^ (t & 6) ^ ((t & 1) << 3)) << 3;
    const uint32_t NB = (uint32_t)(L ^ t ^ ((t & 1) << 3)) << 3;
    char* Sb = (char*)S;
    const uint32_t TB9  = (uint32_t)t << 9;
    const uint32_t TB12 = (uint32_t)t << 12;
    #pragma unroll
    for (int a=0;a<8;a++)
        v[a] = *(float2*)(Sb + (uint32_t)(a<<12) + TB9 + (MB ^ (uint32_t)((a ^ ((a&1)<<3))<<3)));
    fft8<DIR>(v);
    *(float2*)(Sb + TB9 + (MB ^ 0u)) = v[0];
    #pragma unroll
    for (int c=1;c<8;c++)
        *(float2*)(Sb + (uint32_t)(c<<12) + TB9 + (MB ^ (uint32_t)((c ^ ((c&1)<<3))<<3))) = cmul(v[c], w8[c]);
    __syncwarp();
    #pragma unroll
    for (int b=0;b<8;b++)
        v[b] = *(float2*)(Sb + TB12 + (uint32_t)(b<<9) + (NB ^ (uint32_t)((((b&6) ^ ((b&1)<<3)))<<3)));
    fft8<DIR>(v);
    __syncwarp();
    #pragma unroll
    for (int d=0;d<8;d++)
        *(float2*)(Sb + (uint32_t)(d<<12) + TB9 + (MB ^ (uint32_t)((d ^ ((d&1)<<3))<<3))) = v[d];
    __syncthreads();            // before cross-warp epilogue reads
}

__device__ __forceinline__ int band_idx(float f){
    return (int)floorf((f + 1.0f) * 0.5f * 64.0f);
}

// ---------------- kernel A: conv blocks (front) + forward FFT blocks ----------------
// Grid: [0,128)    -> 3x3 conv (b = bx>>1, 32-row tile), no data staging, 1 barrier
//       [128,1664) -> forward FFT, direct gmem row loads, register twiddles
__global__ __launch_bounds__(512) void k_fwdconv(const float* __restrict__ x,
                                                 const float* __restrict__ fbs,
                                                 const float* __restrict__ cw,
                                                 const float* __restrict__ mixp){
    __shared__ float2 S[64*64];
    const int tid = threadIdx.x;

    if (blockIdx.x < 128){
        // ======== 3x3 spatial conv: direct gmem loads, channel pairs in f32x2 ========
        float2* cwS = S;                  // [32][9]
        const int b  = blockIdx.x >> 1;
        const int r0 = (blockIdx.x & 1) * 32;
        for (int k = tid; k < 288; k += 512){
            int cp = k / 9, t = k - cp*9;
            cwS[k] = make_float2(cw[(2*cp)*9 + t], cw[(2*cp+1)*9 + t]);
        }
        __syncthreads();
        const int r  = tid >> 4;          // 0..31
        const int w0 = (tid & 15) * 4;    // 0..60
        const bool mok = (w0 > 0), pok = (w0 < 60);
        float2 acc[4];
        #pragma unroll
        for (int l=0;l<4;l++) acc[l] = make_float2(0.f, 0.f);
        for (int cp = 0; cp < 32; cp++){
            const float* baseA = x + ((size_t)(b*64 + 2*cp) << 12);
            const float* baseB = baseA + 4096;
            float2 c9[9];
            #pragma unroll
            for (int q=0;q<9;q++) c9[q] = cwS[cp*9 + q];
            #pragma unroll
            for (int dy=0; dy<3; dy++){
                const int gr = r0 + r + dy - 1;
                if (gr >= 0 && gr < 64){
                    const float* rowA = baseA + gr*64;
                    const float* rowB = baseB + gr*64;
                    float4 a4 = *(const float4*)(rowA + w0);
                    float4 b4 = *(const float4*)(rowB + w0);
                    float am = mok ? rowA[w0-1] : 0.f;
                    float bm = mok ? rowB[w0-1] : 0.f;
                    float ap = pok ? rowA[w0+4] : 0.f;
                    float bp = pok ? rowB[w0+4] : 0.f;
                    float2 m1 = make_float2(am, bm);
                    float2 v0 = make_float2(a4.x, b4.x);
                    float2 v1 = make_float2(a4.y, b4.y);
                    float2 v2 = make_float2(a4.z, b4.z);
                    float2 v3 = make_float2(a4.w, b4.w);
                    float2 p4 = make_float2(ap, bp);
                    const float2* cr = &c9[dy*3];
                    acc[0] = ffma2(cr[0], m1, acc[0]); acc[0] = ffma2(cr[1], v0, acc[0]); acc[0] = ffma2(cr[2], v1, acc[0]);
                    acc[1] = ffma2(cr[0], v0, acc[1]); acc[1] = ffma2(cr[1], v1, acc[1]); acc[1] = ffma2(cr[2], v2, acc[1]);
                    acc[2] = ffma2(cr[0], v1, acc[2]); acc[2] = ffma2(cr[1], v2, acc[2]); acc[2] = ffma2(cr[2], v3, acc[2]);
                    acc[3] = ffma2(cr[0], v2, acc[3]); acc[3] = ffma2(cr[1], v3, acc[3]); acc[3] = ffma2(cr[2], p4, acc[3]);
                }
            }
        }
        const float c1 = 1.0f - mixp[0];
        float4 outv = make_float4(c1*(acc[0].x+acc[0].y), c1*(acc[1].x+acc[1].y),
                                  c1*(acc[2].x+acc[2].y), c1*(acc[3].x+acc[3].y));
        *(float4*)(g_xsp + b*4096 + (r0 + r)*64 + w0) = outv;
        return;
    }

    // ======== forward FFT ========
    const int bx = blockIdx.x - 128;      // 0..1535
    int pA, qA, pB, qB;
    bool magN, cA = false, cB = false;
    if (bx < 1024){                 // set1: q<32, pairs along p
        int q = bx & 31, m = bx >> 5;
        pA = 2*m;   pB = 2*m + 1;  qA = q; qB = q;
        magN = (pA < 32);
        const int i = q + 32;
        const int bA = (pA + 32) & 63, bB = (pB + 32) & 63;
        cA = (i >= band_idx(fbs[bA*2+0])) && (i < band_idx(fbs[bA*2+1]));
        cB = (i >= band_idx(fbs[bB*2+0])) && (i < band_idx(fbs[bB*2+1]));
        if (!magN && !cA && !cB) return;   // plane pair feeds nothing
    } else {                        // set2: p<32, q>=32, pairs along q (mag only)
        int idx = bx - 1024;
        int p = idx & 31, m = idx >> 5;
        pA = p; pB = p; qA = 32 + 2*m; qB = 33 + 2*m;
        magN = true;
    }
    const int t = tid & 7;
    const int line = tid >> 3;
    float2 w8[8];
    make_tw<-1>(w8, t);
    // row stage-1: direct gmem loads; sign = (-1)^(line+t) (cols step by 8)
    {
        const float sgn = ((line + t) & 1) ? -1.0f : 1.0f;
        const float* pa = x + ((size_t)(pA*64 + qA) << 12) + line*64 + t;
        const float* pb = x + ((size_t)(pB*64 + qB) << 12) + line*64 + t;
        float2 v[8];
        #pragma unroll
        for (int a=0;a<8;a++)
            v[a] = make_float2(pa[a*8]*sgn, pb[a*8]*sgn);
        fft8<-1>(v);
        fft2d_from_rows<-1>(S, v, w8, tid);
    }

    if (bx < 1024){
        const int bA = (pA + 32) & 63, bB = (pB + 32) & 63;
        __half2* dstA = g_XS2 + ((size_t)(bA*32 + qA) << 11);
        __half2* dstB = g_XS2 + ((size_t)(bB*32 + qB) << 11);
        float* magA = g_AB + ((size_t)(pA*64 + (qA + 32)) << 11);
        float* magB = g_AB + ((size_t)(pB*64 + (qB + 32)) << 11);
        for (int k = tid; k < 2048; k += 512){
            const int hh = 32 + (k >> 6);
            const int ww = k & 63;
            const int mh = 64 - hh;
            const int mw = (64 - ww) & 63;
            float2 z  = S[SWA(hh, ww)];
            float2 zp = S[SWA(mh, mw)];
            float2 fa = make_float2(0.5f*(z.x + zp.x), 0.5f*(z.y - zp.y));
            float2 fb = make_float2(0.5f*(z.y + zp.y), 0.5f*(zp.x - z.x));
            if (cA) dstA[k] = __floats2half2_rn(fa.x, fa.y);
            if (cB) dstB[k] = __floats2half2_rn(fb.x, fb.y);
            if (magN){
                magA[k] = sqrtf(fmaf(fa.x, fa.x, fa.y*fa.y));
                magB[k] = sqrtf(fmaf(fb.x, fb.x, fb.y*fb.y));
            }
        }
    } else {
        float* magA = g_AB + ((size_t)(pA*64 + (qA - 32)) << 11);
        float* magB = g_AB + ((size_t)(pB*64 + (qB - 32)) << 11);
        for (int k = tid; k < 2048; k += 512){
            const int hh = 32 + (k >> 6);
            const int ww = k & 63;
            const int mh = 64 - hh;
            const int mw = (64 - ww) & 63;
            float2 z  = S[SWA(hh, ww)];
            float2 zp = S[SWA(mh, mw)];
            float ax = 0.5f*(z.x + zp.x), ay = 0.5f*(z.y - zp.y);
            float bx2 = 0.5f*(z.y + zp.y), by = 0.5f*(zp.x - z.x);
            magA[k] = sqrtf(fmaf(ax, ax, ay*ay));
            magB[k] = sqrtf(fmaf(bx2, bx2, by*by));
        }
    }
}

// ---------------- kernel B: attention matvec + log-Gabor -> Wt ----------------
__global__ __launch_bounds__(256) void k_attn(const float* __restrict__ f0,
        const float* __restrict__ theta, const float* __restrict__ sigma,
        const float* __restrict__ theta0, const float* __restrict__ w1,
        const float* __restrict__ b1, const float* __restrict__ w2,
        const float* __restrict__ b2){
    __shared__ float sA[64*64];   // |xs| tile [c][w]
    __shared__ float sW[64*65];   // w1 [o][c] padded; reused as h1 [o][w]
    __shared__ float sw2[3*64];
    const int io = blockIdx.x & 31, hp = blockIdx.x >> 5;
    const int i = io + 32, h = hp + 32;
    const int tid = threadIdx.x;

    for (int k = tid; k < 4096; k += 256){
        int o = k >> 6, c = k & 63;
        sW[o*65 + c] = w1[k];
    }
    if (tid < 192) sw2[tid] = w2[tid];
    const float* base = g_AB + (((size_t)io*64) << 11) + ((size_t)hp << 6);
    for (int k = tid; k < 4096; k += 256){
        int c = k >> 6, w = k & 63;
        sA[c*64 + w] = base[((size_t)c << 11) + w];
    }
    __syncthreads();

    // h1 = relu(b1 + w1 @ |xs|): f32x2 over the w dimension
    const int tw = tid & 15, to = tid >> 4;
    const int o0 = to*4, w0 = tw*4;
    float2 acc[4][2];
    #pragma unroll
    for (int j=0;j<4;j++){
        float bv = b1[o0+j];
        acc[j][0] = make_float2(bv, bv);
        acc[j][1] = make_float2(bv, bv);
    }
    for (int c=0;c<64;c++){
        float4 av = *(const float4*)&sA[c*64 + w0];
        float2 av01 = make_float2(av.x, av.y);
        float2 av23 = make_float2(av.z, av.w);
        #pragma unroll
        for (int j=0;j<4;j++){
            float wv = sW[(o0+j)*65 + c];
            float2 wv2 = make_float2(wv, wv);
            acc[j][0] = ffma2(wv2, av01, acc[j][0]);
            acc[j][1] = ffma2(wv2, av23, acc[j][1]);
        }
    }
    __syncthreads();
    #pragma unroll
    for (int j=0;j<4;j++){
        sW[(o0+j)*65 + w0+0] = fmaxf(acc[j][0].x, 0.0f);
        sW[(o0+j)*65 + w0+1] = fmaxf(acc[j][0].y, 0.0f);
        sW[(o0+j)*65 + w0+2] = fmaxf(acc[j][1].x, 0.0f);
        sW[(o0+j)*65 + w0+3] = fmaxf(acc[j][1].y, 0.0f);
    }
    __syncthreads();

    // tail: 4 threads per w, shfl-reduced
    {
        const int w = tid >> 2, sub = tid & 3;
        float d0 = 0.f, d1 = 0.f, d2 = 0.f;
        const int ob = sub * 16;
        #pragma unroll
        for (int oo = 0; oo < 16; oo++){
            int o = ob + oo;
            float hv = sW[o*65 + w];
            d0 = fmaf(sw2[o],       hv, d0);
            d1 = fmaf(sw2[64 + o],  hv, d1);
            d2 = fmaf(sw2[128 + o], hv, d2);
        }
        #pragma unroll
        for (int off = 1; off < 4; off <<= 1){
            d0 += __shfl_xor_sync(0xffffffffu, d0, off);
            d1 += __shfl_xor_sync(0xffffffffu, d1, off);
            d2 += __shfl_xor_sync(0xffffffffu, d2, off);
        }
        if (sub == 0){
            float lg0 = d0 + b2[0], lg1 = d1 + b2[1], lg2 = d2 + b2[2];
            float mx = fmaxf(lg0, fmaxf(lg1, lg2));
            float e0 = expf(lg0-mx), e1 = expf(lg1-mx), e2 = expf(lg2-mx);
            float inv = 1.0f/(e0+e1+e2);
            float awv[3] = {e0*inv, e1*inv, e2*inv};
            float yy = 2.0f*(float)h/63.0f - 1.0f;
            float xx = 2.0f*(float)w/63.0f - 1.0f;
            float r2 = fmaf(xx, xx, fmaf(yy, yy, 1e-6f));
            float lr = 0.5f*logf(r2);
            float phi = atan2f(yy, xx);
            float wt = 0.0f;
            #pragma unroll
            for (int s3=0;s3<3;s3++){
                float lf0 = logf(f0[s3*64+i]);
                float ls  = logf(sigma[s3*64+i]);
                float d1v = lr - lf0;
                float g  = expf(-(d1v*d1v)/(2.0f*ls*ls));
                float d2v = phi - theta[s3*64+i];
                float t0v = theta0[s3*64+i];
                float ang = expf(-(d2v*d2v)/(2.0f*t0v*t0v));
                wt = fmaf(g*ang, awv[s3], wt);
            }
            g_Wt[(io*32 + hp)*64 + w] = wt;
        }
    }
}

// ---------------- kernel D: merged output (copy OR masked IFFT + mix) ----------------
__global__ __launch_bounds__(512) void k_out(const float* __restrict__ fbs,
        const float* __restrict__ mixp, float* __restrict__ out){
    const int bo = blockIdx.x >> 6, ioo = blockIdx.x & 63;
    const int b = (bo + 32) & 63, i = (ioo + 32) & 63;   // ifftshift of batch/channel dims
    const int sidx = band_idx(fbs[b*2+0]);               // in [32,64)
    const int eidx = band_idx(fbs[b*2+1]);
    const int tid = threadIdx.x;
    float* o = out + ((size_t)blockIdx.x << 12);
    const float* sp = g_xsp + bo*4096;                   // already scaled by (1-mix)
    if (i < sidx || i >= eidx){
        const float4* sp4 = (const float4*)sp;
        float4* o4 = (float4*)o;
        o4[tid]       = sp4[tid];
        o4[tid + 512] = sp4[tid + 512];
        return;
    }
    __shared__ float2 S[64*64];
    const float mix = mixp[0];
    const int t = tid & 7;
    const int line = tid >> 3;
    float2 w8[8];
    make_tw<1>(w8, t);
    // row stage-1: rows in [sidx,eidx) load weighted spectrum; others are zero
    {
        float2 v[8];
        if (line >= sidx && line < eidx){
            const __half2* src = g_XS2 + ((size_t)(b*32 + (i-32)) << 11) + (line-32)*64 + t;
            const float*   wr  = g_Wt + ((i-32)*32 + (line-32))*64 + t;
            #pragma unroll
            for (int a=0;a<8;a++){
                float2 z = __half22float2(src[a*8]);
                float wv = wr[a*8];
                v[a] = make_float2(z.x*wv, z.y*wv);
            }
            fft8<1>(v);
        } else {
            #pragma unroll
            for (int a=0;a<8;a++) v[a] = make_float2(0.0f, 0.0f);
        }
        fft2d_from_rows<1>(S, v, w8, tid);
    }
    const float sc = mix * (1.0f/4096.0f);
    for (int k = tid; k < 4096; k += 512){
        int yy = k >> 6, xx = k & 63;
        float par = ((yy + xx) & 1) ? -sc : sc;          // ifftshift(h,w) modulation
        o[k] = fmaf(par, S[SWA(yy, xx)].x, sp[k]);
    }
}

// ---------------- launch ----------------
extern "C" void kernel_launch(void* const* d_in, const int* in_sizes, int n_in,
                              void* d_out, int out_size){
    (void)in_sizes; (void)n_in; (void)out_size;
    const float* x      = (const float*)d_in[0];
    const float* f0     = (const float*)d_in[1];
    const float* theta  = (const float*)d_in[2];
    const float* sigma  = (const float*)d_in[3];
    const float* theta0 = (const float*)d_in[4];
    const float* fbs    = (const float*)d_in[5];
    const float* mix    = (const float*)d_in[6];
    const float* w1     = (const float*)d_in[7];
    const float* b1     = (const float*)d_in[8];
    const float* w2     = (const float*)d_in[9];
    const float* b2     = (const float*)d_in[10];
    const float* cw     = (const float*)d_in[11];
    float* out = (float*)d_out;

    k_fwdconv<<<1664, 512>>>(x, fbs, cw, mix);
    k_attn<<<1024, 256>>>(f0, theta, sigma, theta0, w1, b1, w2, b2);
    k_out<<<4096, 512>>>(fbs, mix, out);
}